// round 6
// baseline (speedup 1.0000x reference)
#include <cuda_runtime.h>
#include <cstdint>
#include <math.h>

// Problem constants
#define BB    2
#define SS    2048
#define HH    4096
#define NHEAD 32
#define DD    128
#define MTOT  (BB*SS)

// Scratch (no cudaMalloc allowed)
__device__ float g_Q[(size_t)BB*SS*HH];     // 64 MB
__device__ float g_K[(size_t)BB*SS*DD];     // 2 MB
__device__ float g_V[(size_t)BB*SS*DD];     // 2 MB
__device__ float g_attn[(size_t)BB*SS*HH];  // 64 MB (scrambled layout)
__device__ float g_part[(size_t)4*MTOT*DD]; // 8 MB split-K partials

// ===========================================================================
// Helpers
// ===========================================================================
// tf32 mma.sync: D(16x8) += A(16x8) @ B(8x8), row.col, fp32 accum
__device__ __forceinline__ void mma_tf32(float* d, const uint32_t* a, const uint32_t* b) {
    asm volatile(
        "mma.sync.aligned.m16n8k8.row.col.f32.tf32.tf32.f32 "
        "{%0,%1,%2,%3}, {%4,%5,%6,%7}, {%8,%9}, {%0,%1,%2,%3};"
        : "+f"(d[0]), "+f"(d[1]), "+f"(d[2]), "+f"(d[3])
        : "r"(a[0]), "r"(a[1]), "r"(a[2]), "r"(a[3]), "r"(b[0]), "r"(b[1]));
}

// Dekker split: a = hi + lo (both tf32-representable), returned as float bits
__device__ __forceinline__ float2 split2_tf32(float a) {
    uint32_t h;
    asm("cvt.rna.tf32.f32 %0, %1;" : "=r"(h) : "f"(a));
    float l = a - __uint_as_float(h);
    uint32_t l32;
    asm("cvt.rna.tf32.f32 %0, %1;" : "=r"(l32) : "f"(l));
    return make_float2(__uint_as_float(h), __uint_as_float(l32));
}

// ===========================================================================
// 3xTF32 tensor-core GEMM, v3:
//   C[M,N] = A[M,K] @ W[N,K]^T (+ bias[N] when gridDim.z == 1)
// CTA 128x128, K-chunk 32, 8 warps (2x4), warp 64x32, double-buffered smem.
// Dekker split hoisted to STORE time; smem holds interleaved (hi,lo) pairs in
// fragment-permuted layout so the inner loop is pure lds.128 + mma.
//   A tile (16 rows x 8 k): 8 phys rows (stride 36), tile stride 296 floats.
//     elem(rr,kl): off = (rr&7)*36 + (kl&3)*8 + ((kl>>2)<<2) + ((rr>>3)<<1) + hilo
//     frag: lds.128 @ tile*296 + g*36 + t*8      -> {a0h,a0l,a1h,a1l}
//           lds.128 @ ... + 4                    -> {a2h,a2l,a3h,a3l}
//   B tile (8 n x 8 k): tile id = tn*4+tk, stride 136 floats.
//     elem(nn,kl): off = nn*16 + (kl&3)*4 + ((kl>>2)<<1) + hilo
//     frag: lds.128 @ tile*136 + g*16 + t*4      -> {b0h,b0l,b1h,b1l}
// Fragment lds phases are bank-conflict-free (row strides 36 / 16 mod 32).
// Split-K: blockIdx.z selects K segment of kLen; partials to C + z*M*N.
// ===========================================================================
#define A_TILE_STRIDE 296
#define B_TILE_STRIDE 136
#define A_BUF  (32*A_TILE_STRIDE)           // 9472 floats
#define B_BUF  (64*B_TILE_STRIDE)           // 8704 floats
#define BUF_FLOATS (A_BUF + B_BUF)          // 18176
#define GEMM_SMEM_BYTES (2*BUF_FLOATS*4)    // 145408 B

__global__ void __launch_bounds__(256, 1)
gemm_tf32_mma(const float* __restrict__ A, const float* __restrict__ W,
              const float* __restrict__ bias, float* __restrict__ C,
              int M, int N, int Kdim, int kLen)
{
    extern __shared__ float smem[];

    const int tid = threadIdx.x;
    const int wid = tid >> 5;
    const int lane = tid & 31;
    const int g = lane >> 2;       // 0..7
    const int t = lane & 3;        // 0..3
    const int wm = wid & 1;
    const int wn = wid >> 1;
    const int m0 = blockIdx.y * 128;
    const int n0 = blockIdx.x * 128;
    const int kOff = blockIdx.z * kLen;

    float acc[4][4][4];
    #pragma unroll
    for (int i = 0; i < 4; i++)
        #pragma unroll
        for (int j = 0; j < 4; j++)
            #pragma unroll
            for (int r = 0; r < 4; r++) acc[i][j][r] = 0.f;

    const int nch = kLen >> 5;
    const int crow = tid >> 3;     // row base (0..31), +32 per tt
    const int ckg  = tid & 7;      // 4-float k group (0..7)

    float4 pa[4], pb[4];

    // ---- prologue: LDG chunk 0
    #pragma unroll
    for (int tt = 0; tt < 4; tt++) {
        int r = crow + tt * 32;
        pa[tt] = *(const float4*)(A + (size_t)(m0 + r) * Kdim + kOff + ckg * 4);
        pb[tt] = *(const float4*)(W + (size_t)(n0 + r) * Kdim + kOff + ckg * 4);
    }

    // Precomputed store bases (depend only on tid)
    const int a_tm = crow >> 4;            // for tt: tm = (crow+32tt)>>4 = a_tm + 2tt
    const int a_rr0 = crow & 15;
    const int a_tk = ckg >> 1;
    const int a_sub = ((ckg & 1) << 2);
    const int b_tn0 = crow >> 3;           // tn = b_tn0 + 4tt
    const int b_nn = crow & 7;
    const int b_sub = ((ckg & 1) << 1);

    for (int c = 0; c < nch; c++) {
        float* sbuf = smem + (c & 1) * BUF_FLOATS;
        float* sA = sbuf;
        float* sB = sbuf + A_BUF;

        // split + STS (chunk c)
        #pragma unroll
        for (int tt = 0; tt < 4; tt++) {
            {   // A
                int tm = a_tm + 2 * tt;
                float* base = sA + (tm * 4 + a_tk) * A_TILE_STRIDE
                            + (a_rr0 & 7) * 36 + a_sub + ((a_rr0 >> 3) << 1);
                *(float2*)(base + 0)  = split2_tf32(pa[tt].x);
                *(float2*)(base + 8)  = split2_tf32(pa[tt].y);
                *(float2*)(base + 16) = split2_tf32(pa[tt].z);
                *(float2*)(base + 24) = split2_tf32(pa[tt].w);
            }
            {   // B
                int tn = b_tn0 + 4 * tt;
                float* base = sB + (tn * 4 + a_tk) * B_TILE_STRIDE
                            + b_nn * 16 + b_sub;
                *(float2*)(base + 0)  = split2_tf32(pb[tt].x);
                *(float2*)(base + 4)  = split2_tf32(pb[tt].y);
                *(float2*)(base + 8)  = split2_tf32(pb[tt].z);
                *(float2*)(base + 12) = split2_tf32(pb[tt].w);
            }
        }
        __syncthreads();

        // prefetch chunk c+1 (latency hidden by compute below)
        if (c + 1 < nch) {
            const int k0 = kOff + ((c + 1) << 5);
            #pragma unroll
            for (int tt = 0; tt < 4; tt++) {
                int r = crow + tt * 32;
                pa[tt] = *(const float4*)(A + (size_t)(m0 + r) * Kdim + k0 + ckg * 4);
                pb[tt] = *(const float4*)(W + (size_t)(n0 + r) * Kdim + k0 + ckg * 4);
            }
        }

        // compute chunk c: pure lds.128 + mma
        #pragma unroll
        for (int ks = 0; ks < 4; ks++) {
            uint32_t ah[4][4], al[4][4];
            #pragma unroll
            for (int mt = 0; mt < 4; mt++) {
                const float* tp = sA + ((wm * 4 + mt) * 4 + ks) * A_TILE_STRIDE
                                + g * 36 + t * 8;
                float4 f1 = *(const float4*)tp;
                float4 f2 = *(const float4*)(tp + 4);
                ah[mt][0] = __float_as_uint(f1.x); al[mt][0] = __float_as_uint(f1.y);
                ah[mt][1] = __float_as_uint(f1.z); al[mt][1] = __float_as_uint(f1.w);
                ah[mt][2] = __float_as_uint(f2.x); al[mt][2] = __float_as_uint(f2.y);
                ah[mt][3] = __float_as_uint(f2.z); al[mt][3] = __float_as_uint(f2.w);
            }
            uint32_t bh[4][2], bl[4][2];
            #pragma unroll
            for (int tn = 0; tn < 4; tn++) {
                const float* tp = sB + ((wn * 4 + tn) * 4 + ks) * B_TILE_STRIDE
                                + g * 16 + t * 4;
                float4 f = *(const float4*)tp;
                bh[tn][0] = __float_as_uint(f.x); bl[tn][0] = __float_as_uint(f.y);
                bh[tn][1] = __float_as_uint(f.z); bl[tn][1] = __float_as_uint(f.w);
            }
            #pragma unroll
            for (int mt = 0; mt < 4; mt++)
                #pragma unroll
                for (int tn = 0; tn < 4; tn++) {
                    mma_tf32(acc[mt][tn], al[mt], bh[tn]);
                    mma_tf32(acc[mt][tn], ah[mt], bl[tn]);
                    mma_tf32(acc[mt][tn], ah[mt], bh[tn]);
                }
        }
    }

    // Epilogue
    const bool full = (gridDim.z == 1);
    float* Cout = C + (full ? (size_t)0 : (size_t)blockIdx.z * M * N);
    #pragma unroll
    for (int mt = 0; mt < 4; mt++) {
        int row = m0 + wm * 64 + mt * 16 + g;
        #pragma unroll
        for (int tn = 0; tn < 4; tn++) {
            int col = n0 + wn * 32 + tn * 8 + t * 2;
            float bx = 0.f, by = 0.f;
            if (full) { float2 bv = *(const float2*)(bias + col); bx = bv.x; by = bv.y; }
            float2 v0, v1;
            v0.x = acc[mt][tn][0] + bx; v0.y = acc[mt][tn][1] + by;
            v1.x = acc[mt][tn][2] + bx; v1.y = acc[mt][tn][3] + by;
            *(float2*)(Cout + (size_t)row * N + col) = v0;
            *(float2*)(Cout + (size_t)(row + 8) * N + col) = v1;
        }
    }
}

// Deterministic split-K reduce: out[i] = sum_{s<4} part[s][i] + bias[i % N]
__global__ void __launch_bounds__(256)
reduce4_bias(const float* __restrict__ part, const float* __restrict__ bias,
             float* __restrict__ out, int MN, int N)
{
    int i = blockIdx.x * 256 + threadIdx.x;
    if (i < MN) {
        float v = (part[i] + part[(size_t)MN + i])
                + (part[(size_t)2*MN + i] + part[(size_t)3*MN + i]);
        out[i] = v + bias[i & (N - 1)];
    }
}

// ---------------------------------------------------------------------------
// Fused MQA flash attention, fp32. BQ=64, BKV=32, 2 CTAs/SM. (validated R4/R5)
// Epilogue stores scrambled layout: A[b, h*64 + d/2, (d&1)*2048 + q0 + s]
// ---------------------------------------------------------------------------
#define ATTN_SMEM_FLOATS (8448 + 4224 + 4224 + 64*36)   // 76800 B

__global__ void __launch_bounds__(256, 2)
mqa_attn_kernel(const float* __restrict__ Q, const float* __restrict__ Kg,
                const float* __restrict__ Vg, float* __restrict__ Outp)
{
    extern __shared__ float sm[];
    float* Qs = sm;             // [64][132]
    float* Ks = sm + 8448;      // [32][132]
    float* Vs = sm + 12672;     // [32][132]
    float* Ps = sm + 16896;     // [64][36]

    const int tid = threadIdx.x;
    const int qt  = blockIdx.x;
    const int h   = blockIdx.y;
    const int b   = blockIdx.z;
    const int tx  = tid & 15;
    const int ty  = tid >> 4;

    const float scale = 0.08838834764831845f;
    const int q0 = qt * 64;

    const size_t qbase = ((size_t)b*SS + q0)*HH + (size_t)h*DD;
    for (int i = tid; i < 64*128; i += 256) {
        int r = i >> 7, d = i & 127;
        Qs[r*132 + d] = Q[qbase + (size_t)r*HH + d] * scale;
    }

    float m_i[4], l_i[4], acc_o[4][8];
    #pragma unroll
    for (int i = 0; i < 4; i++) {
        m_i[i] = -INFINITY; l_i[i] = 0.f;
        #pragma unroll
        for (int j = 0; j < 8; j++) acc_o[i][j] = 0.f;
    }

    const size_t kvbase0 = (size_t)b*SS*DD;

    for (int kt = 0; kt < SS/32; kt++) {
        __syncthreads();
        const size_t kvb = kvbase0 + (size_t)kt*32*DD;
        for (int i = tid; i < 32*128; i += 256) {
            int r = i >> 7, d = i & 127;
            Ks[r*132 + d] = Kg[kvb + i];
            Vs[r*132 + d] = Vg[kvb + i];
        }
        __syncthreads();

        float sa[4][2];
        #pragma unroll
        for (int i = 0; i < 4; i++) { sa[i][0] = 0.f; sa[i][1] = 0.f; }

        #pragma unroll 8
        for (int d = 0; d < 128; d += 4) {
            float4 qv[4], kv[2];
            #pragma unroll
            for (int i = 0; i < 4; i++) qv[i] = *(const float4*)&Qs[(ty*4+i)*132 + d];
            #pragma unroll
            for (int j = 0; j < 2; j++) kv[j] = *(const float4*)&Ks[(tx*2+j)*132 + d];
            #pragma unroll
            for (int i = 0; i < 4; i++)
                #pragma unroll
                for (int j = 0; j < 2; j++)
                    sa[i][j] += qv[i].x*kv[j].x + qv[i].y*kv[j].y
                              + qv[i].z*kv[j].z + qv[i].w*kv[j].w;
        }

        #pragma unroll
        for (int i = 0; i < 4; i++) {
            float tmax = fmaxf(sa[i][0], sa[i][1]);
            #pragma unroll
            for (int off = 8; off >= 1; off >>= 1)
                tmax = fmaxf(tmax, __shfl_xor_sync(0xffffffffu, tmax, off, 16));
            float mnew  = fmaxf(m_i[i], tmax);
            float alpha = __expf(m_i[i] - mnew);
            float rsum;
            sa[i][0] = __expf(sa[i][0] - mnew);
            sa[i][1] = __expf(sa[i][1] - mnew);
            rsum = sa[i][0] + sa[i][1];
            #pragma unroll
            for (int off = 8; off >= 1; off >>= 1)
                rsum += __shfl_xor_sync(0xffffffffu, rsum, off, 16);
            l_i[i] = l_i[i]*alpha + rsum;
            m_i[i] = mnew;
            #pragma unroll
            for (int j = 0; j < 8; j++) acc_o[i][j] *= alpha;
            *(float2*)&Ps[(ty*4+i)*36 + tx*2] = make_float2(sa[i][0], sa[i][1]);
        }
        __syncthreads();

        #pragma unroll 2
        for (int kv4 = 0; kv4 < 32; kv4 += 4) {
            float4 pv[4];
            #pragma unroll
            for (int i = 0; i < 4; i++) pv[i] = *(const float4*)&Ps[(ty*4+i)*36 + kv4];
            #pragma unroll
            for (int u = 0; u < 4; u++) {
                float4 v0 = *(const float4*)&Vs[(kv4+u)*132 + tx*8];
                float4 v1 = *(const float4*)&Vs[(kv4+u)*132 + tx*8 + 4];
                #pragma unroll
                for (int i = 0; i < 4; i++) {
                    float p = (u == 0) ? pv[i].x : (u == 1) ? pv[i].y
                            : (u == 2) ? pv[i].z : pv[i].w;
                    acc_o[i][0] += p*v0.x; acc_o[i][1] += p*v0.y;
                    acc_o[i][2] += p*v0.z; acc_o[i][3] += p*v0.w;
                    acc_o[i][4] += p*v1.x; acc_o[i][5] += p*v1.y;
                    acc_o[i][6] += p*v1.z; acc_o[i][7] += p*v1.w;
                }
            }
        }
    }

    __syncthreads();
    #pragma unroll
    for (int i = 0; i < 4; i++) {
        float inv = 1.f / l_i[i];
        #pragma unroll
        for (int j = 0; j < 8; j++) acc_o[i][j] *= inv;
        int r = ty*4 + i;
        *(float4*)&Qs[r*132 + tx*8]     = make_float4(acc_o[i][0], acc_o[i][1], acc_o[i][2], acc_o[i][3]);
        *(float4*)&Qs[r*132 + tx*8 + 4] = make_float4(acc_o[i][4], acc_o[i][5], acc_o[i][6], acc_o[i][7]);
    }
    __syncthreads();

    const size_t obase = (size_t)b*SS*HH;
    for (int i = tid; i < 64*128; i += 256) {
        int d = i >> 6;
        int s = i & 63;
        size_t row = (size_t)h*64 + (d >> 1);
        size_t col = (size_t)(d & 1)*2048 + q0 + s;
        Outp[obase + row*HH + col] = Qs[s*132 + d];
    }
}

// ---------------------------------------------------------------------------
extern "C" void kernel_launch(void* const* d_in, const int* in_sizes, int n_in,
                              void* d_out, int out_size)
{
    const float* X  = (const float*)d_in[0];
    const float* Wq = (const float*)d_in[1];
    const float* bq = (const float*)d_in[2];
    const float* Wk = (const float*)d_in[3];
    const float* bk = (const float*)d_in[4];
    const float* Wv = (const float*)d_in[5];
    const float* bv = (const float*)d_in[6];
    const float* Wo = (const float*)d_in[7];
    const float* bo = (const float*)d_in[8];
    float* out = (float*)d_out;

    float *Qp, *Kp, *Vp, *Ap, *Pp;
    cudaGetSymbolAddress((void**)&Qp, g_Q);
    cudaGetSymbolAddress((void**)&Kp, g_K);
    cudaGetSymbolAddress((void**)&Vp, g_V);
    cudaGetSymbolAddress((void**)&Ap, g_attn);
    cudaGetSymbolAddress((void**)&Pp, g_part);

    cudaFuncSetAttribute(gemm_tf32_mma,
                         cudaFuncAttributeMaxDynamicSharedMemorySize, GEMM_SMEM_BYTES);
    cudaFuncSetAttribute(mqa_attn_kernel,
                         cudaFuncAttributeMaxDynamicSharedMemorySize,
                         ATTN_SMEM_FLOATS * (int)sizeof(float));

    // 1) Q projection (full K)
    gemm_tf32_mma<<<dim3(HH/128, MTOT/128, 1), 256, GEMM_SMEM_BYTES>>>(
        X, Wq, bq, Qp, MTOT, HH, HH, HH);

    // 2) K projection (split-K=4 -> partials -> reduce+bias)
    gemm_tf32_mma<<<dim3(DD/128, MTOT/128, 4), 256, GEMM_SMEM_BYTES>>>(
        X, Wk, nullptr, Pp, MTOT, DD, HH, HH/4);
    reduce4_bias<<<(MTOT*DD + 255)/256, 256>>>(Pp, bk, Kp, MTOT*DD, DD);

    // 3) V projection (split-K=4)
    gemm_tf32_mma<<<dim3(DD/128, MTOT/128, 4), 256, GEMM_SMEM_BYTES>>>(
        X, Wv, nullptr, Pp, MTOT, DD, HH, HH/4);
    reduce4_bias<<<(MTOT*DD + 255)/256, 256>>>(Pp, bv, Vp, MTOT*DD, DD);

    // 4) Fused attention (fp32, BKV=32, 2 CTAs/SM)
    mqa_attn_kernel<<<dim3(SS/64, NHEAD, BB), 256,
                      ATTN_SMEM_FLOATS * sizeof(float)>>>(Qp, Kp, Vp, Ap);

    // 5) Output projection (full K)
    gemm_tf32_mma<<<dim3(HH/128, MTOT/128, 1), 256, GEMM_SMEM_BYTES>>>(
        Ap, Wo, bo, out, MTOT, HH, HH, HH);
}

// round 7
// speedup vs baseline: 1.0506x; 1.0506x over previous
#include <cuda_runtime.h>
#include <cstdint>
#include <math.h>

// Problem constants
#define BB    2
#define SS    2048
#define HH    4096
#define NHEAD 32
#define DD    128
#define MTOT  (BB*SS)

// Scratch (no cudaMalloc allowed)
__device__ float g_Q[(size_t)BB*SS*HH];       // 64 MB
__device__ float g_K[(size_t)BB*SS*DD];       // 2 MB
__device__ float g_V[(size_t)BB*SS*DD];       // 2 MB
__device__ float g_attn[(size_t)BB*SS*HH];    // 64 MB (scrambled layout)
__device__ float g_part[(size_t)4*MTOT*DD];   // 8 MB split-K partials
__device__ float g_Asplit[(size_t)2*MTOT*HH]; // 128 MB (X split; reused for attn split)
__device__ float g_Wsplit[(size_t)2*HH*HH];   // 128 MB (Wq/Wk/Wv/Wo split, sequential reuse)

// ===========================================================================
// Helpers
// ===========================================================================
__device__ __forceinline__ uint32_t smem_u32(const void* p) {
    uint32_t a;
    asm("{ .reg .u64 t; cvta.to.shared.u64 t, %1; cvt.u32.u64 %0, t; }" : "=r"(a) : "l"(p));
    return a;
}
__device__ __forceinline__ void cp_async16(uint32_t dst, const void* src) {
    asm volatile("cp.async.cg.shared.global [%0], [%1], 16;" :: "r"(dst), "l"(src));
}

// tf32 mma.sync: D(16x8) += A(16x8) @ B(8x8), row.col, fp32 accum
__device__ __forceinline__ void mma_tf32(float* d, const uint32_t* a, const uint32_t* b) {
    asm volatile(
        "mma.sync.aligned.m16n8k8.row.col.f32.tf32.tf32.f32 "
        "{%0,%1,%2,%3}, {%4,%5,%6,%7}, {%8,%9}, {%0,%1,%2,%3};"
        : "+f"(d[0]), "+f"(d[1]), "+f"(d[2]), "+f"(d[3])
        : "r"(a[0]), "r"(a[1]), "r"(a[2]), "r"(a[3]), "r"(b[0]), "r"(b[1]));
}

// Dekker split: a = hi + lo (both tf32-representable)
__device__ __forceinline__ float2 split2_tf32(float a) {
    uint32_t h;
    asm("cvt.rna.tf32.f32 %0, %1;" : "=r"(h) : "f"(a));
    float l = a - __uint_as_float(h);
    uint32_t l32;
    asm("cvt.rna.tf32.f32 %0, %1;" : "=r"(l32) : "f"(l));
    return make_float2(__uint_as_float(h), __uint_as_float(l32));
}

// ===========================================================================
// Pre-pass: split fp32 array into interleaved (hi,lo) pairs.
// out[2i] = hi(in[i]), out[2i+1] = lo(in[i]).  Vectorized 2 in -> 4 out.
// ===========================================================================
__global__ void __launch_bounds__(256)
split_pack(const float* __restrict__ in, float* __restrict__ out, int n2)
{
    int i = blockIdx.x * 256 + threadIdx.x;   // index over float2 pairs
    if (i < n2) {
        float2 v = *(const float2*)(in + (size_t)i * 2);
        float2 s0 = split2_tf32(v.x);
        float2 s1 = split2_tf32(v.y);
        float4 o = make_float4(s0.x, s0.y, s1.x, s1.y);
        *(float4*)(out + (size_t)i * 4) = o;
    }
}

// ===========================================================================
// 3xTF32 tensor-core GEMM v4: operands are PRE-SPLIT interleaved arrays.
//   C[M,N] = A[M,K] @ W[N,K]^T (+ bias[N] when gridDim.z == 1)
// As/Ws layout: row r, k-element k -> (hi,lo) at [r*2K + 2k].
// CTA 128x128, K-chunk 32 (=64 floats/row), cp.async double-buffered.
// Smem tile [128][72] floats (64 data + 8 pad; stride 72 -> lds.64 fragment
// loads are bank-conflict-free: banks (8g+2t) distinct per half-warp).
// Inner loop: pure lds.64 + mma (no cvt/sub/STS).
// Split-K: blockIdx.z picks K segment of kLen; partials to C + z*M*N.
// ===========================================================================
#define TSTRIDE 72
#define TILE_FLOATS (128*TSTRIDE)               // 9216
#define STAGE_FLOATS (2*TILE_FLOATS)            // A+B = 18432
#define GEMM_SMEM_BYTES (2*STAGE_FLOATS*4)      // 147456 B

__global__ void __launch_bounds__(256, 1)
gemm_tf32_mma(const float* __restrict__ As, const float* __restrict__ Ws,
              const float* __restrict__ bias, float* __restrict__ C,
              int M, int N, int Kdim, int kLen)
{
    extern __shared__ float smem[];
    const uint32_t smem_base = smem_u32(smem);

    const int tid = threadIdx.x;
    const int wid = tid >> 5;
    const int lane = tid & 31;
    const int g = lane >> 2;       // 0..7
    const int t = lane & 3;        // 0..3
    const int wm = wid & 1;
    const int wn = wid >> 1;
    const int m0 = blockIdx.y * 128;
    const int n0 = blockIdx.x * 128;
    const int kOff = blockIdx.z * kLen;

    const size_t K2 = (size_t)Kdim * 2;

    float acc[4][4][4];
    #pragma unroll
    for (int i = 0; i < 4; i++)
        #pragma unroll
        for (int j = 0; j < 4; j++)
            #pragma unroll
            for (int r = 0; r < 4; r++) acc[i][j][r] = 0.f;

    const int nch = kLen >> 5;

    // Copy indices: each thread moves 8 x 16B per tile.
    // pass p (0..7): row = (tid>>4) + p*16, 16B-chunk = tid & 15 (of 16 per row)
    const int crow0 = tid >> 4;
    const int cch   = tid & 15;

    const float* Abase = As + (size_t)m0 * K2 + (size_t)kOff * 2 + cch * 4;
    const float* Wbase = Ws + (size_t)n0 * K2 + (size_t)kOff * 2 + cch * 4;
    const uint32_t sdst0 = smem_base + (uint32_t)(crow0 * TSTRIDE + cch * 4) * 4u;

    // ---- prologue: stage chunk 0 into buffer 0
    #pragma unroll
    for (int p = 0; p < 8; p++) {
        int r = crow0 + p * 16;
        uint32_t doff = sdst0 + (uint32_t)(p * 16 * TSTRIDE) * 4u;
        cp_async16(doff,                               Abase + (size_t)r * K2);
        cp_async16(doff + (uint32_t)TILE_FLOATS * 4u,  Wbase + (size_t)r * K2);
    }
    asm volatile("cp.async.commit_group;" ::: "memory");

    for (int c = 0; c < nch; c++) {
        const int buf = c & 1;
        if (c + 1 < nch) {
            const uint32_t nb = (uint32_t)((c + 1) & 1) * ((uint32_t)STAGE_FLOATS * 4u);
            const size_t ksrc = (size_t)(c + 1) * 64;   // 64 floats per chunk
            #pragma unroll
            for (int p = 0; p < 8; p++) {
                int r = crow0 + p * 16;
                uint32_t doff = sdst0 + nb + (uint32_t)(p * 16 * TSTRIDE) * 4u;
                cp_async16(doff,                              Abase + (size_t)r * K2 + ksrc);
                cp_async16(doff + (uint32_t)TILE_FLOATS * 4u, Wbase + (size_t)r * K2 + ksrc);
            }
            asm volatile("cp.async.commit_group;" ::: "memory");
            asm volatile("cp.async.wait_group 1;" ::: "memory");
        } else {
            asm volatile("cp.async.wait_group 0;" ::: "memory");
        }
        __syncthreads();

        const float* a_s = smem + buf * STAGE_FLOATS;
        const float* b_s = a_s + TILE_FLOATS;

        #pragma unroll
        for (int ks = 0; ks < 4; ks++) {
            const int kb = ks * 16;    // 8 k-elems * 2 floats
            uint32_t ah[4][4], al[4][4];
            #pragma unroll
            for (int mt = 0; mt < 4; mt++) {
                const int r0 = (wm * 64 + mt * 16 + g) * TSTRIDE + kb + t * 2;
                float2 f0 = *(const float2*)(a_s + r0);                 // (g,   t)
                float2 f1 = *(const float2*)(a_s + r0 + 8 * TSTRIDE);   // (g+8, t)
                float2 f2 = *(const float2*)(a_s + r0 + 8);             // (g,   t+4)
                float2 f3 = *(const float2*)(a_s + r0 + 8 * TSTRIDE + 8);
                ah[mt][0] = __float_as_uint(f0.x); al[mt][0] = __float_as_uint(f0.y);
                ah[mt][1] = __float_as_uint(f1.x); al[mt][1] = __float_as_uint(f1.y);
                ah[mt][2] = __float_as_uint(f2.x); al[mt][2] = __float_as_uint(f2.y);
                ah[mt][3] = __float_as_uint(f3.x); al[mt][3] = __float_as_uint(f3.y);
            }
            uint32_t bh[4][2], bl[4][2];
            #pragma unroll
            for (int tn = 0; tn < 4; tn++) {
                const int nb2 = (wn * 32 + tn * 8 + g) * TSTRIDE + kb + t * 2;
                float2 f0 = *(const float2*)(b_s + nb2);        // (n=g, k=t)
                float2 f1 = *(const float2*)(b_s + nb2 + 8);    // (n=g, k=t+4)
                bh[tn][0] = __float_as_uint(f0.x); bl[tn][0] = __float_as_uint(f0.y);
                bh[tn][1] = __float_as_uint(f1.x); bl[tn][1] = __float_as_uint(f1.y);
            }
            #pragma unroll
            for (int mt = 0; mt < 4; mt++)
                #pragma unroll
                for (int tn = 0; tn < 4; tn++) {
                    mma_tf32(acc[mt][tn], al[mt], bh[tn]);
                    mma_tf32(acc[mt][tn], ah[mt], bl[tn]);
                    mma_tf32(acc[mt][tn], ah[mt], bh[tn]);
                }
        }
        __syncthreads();
    }

    // Epilogue
    const bool full = (gridDim.z == 1);
    float* Cout = C + (full ? (size_t)0 : (size_t)blockIdx.z * M * N);
    #pragma unroll
    for (int mt = 0; mt < 4; mt++) {
        int row = m0 + wm * 64 + mt * 16 + g;
        #pragma unroll
        for (int tn = 0; tn < 4; tn++) {
            int col = n0 + wn * 32 + tn * 8 + t * 2;
            float bx = 0.f, by = 0.f;
            if (full) { float2 bv = *(const float2*)(bias + col); bx = bv.x; by = bv.y; }
            float2 v0, v1;
            v0.x = acc[mt][tn][0] + bx; v0.y = acc[mt][tn][1] + by;
            v1.x = acc[mt][tn][2] + bx; v1.y = acc[mt][tn][3] + by;
            *(float2*)(Cout + (size_t)row * N + col) = v0;
            *(float2*)(Cout + (size_t)(row + 8) * N + col) = v1;
        }
    }
}

// Deterministic split-K reduce: out[i] = sum_{s<4} part[s][i] + bias[i % N]
__global__ void __launch_bounds__(256)
reduce4_bias(const float* __restrict__ part, const float* __restrict__ bias,
             float* __restrict__ out, int MN, int N)
{
    int i = blockIdx.x * 256 + threadIdx.x;
    if (i < MN) {
        float v = (part[i] + part[(size_t)MN + i])
                + (part[(size_t)2*MN + i] + part[(size_t)3*MN + i]);
        out[i] = v + bias[i & (N - 1)];
    }
}

// ---------------------------------------------------------------------------
// Fused MQA flash attention, fp32. BQ=64, BKV=32, 2 CTAs/SM. (validated R4/R5)
// Epilogue stores scrambled layout: A[b, h*64 + d/2, (d&1)*2048 + q0 + s]
// ---------------------------------------------------------------------------
#define ATTN_SMEM_FLOATS (8448 + 4224 + 4224 + 64*36)   // 76800 B

__global__ void __launch_bounds__(256, 2)
mqa_attn_kernel(const float* __restrict__ Q, const float* __restrict__ Kg,
                const float* __restrict__ Vg, float* __restrict__ Outp)
{
    extern __shared__ float sm[];
    float* Qs = sm;             // [64][132]
    float* Ks = sm + 8448;      // [32][132]
    float* Vs = sm + 12672;     // [32][132]
    float* Ps = sm + 16896;     // [64][36]

    const int tid = threadIdx.x;
    const int qt  = blockIdx.x;
    const int h   = blockIdx.y;
    const int b   = blockIdx.z;
    const int tx  = tid & 15;
    const int ty  = tid >> 4;

    const float scale = 0.08838834764831845f;
    const int q0 = qt * 64;

    const size_t qbase = ((size_t)b*SS + q0)*HH + (size_t)h*DD;
    for (int i = tid; i < 64*128; i += 256) {
        int r = i >> 7, d = i & 127;
        Qs[r*132 + d] = Q[qbase + (size_t)r*HH + d] * scale;
    }

    float m_i[4], l_i[4], acc_o[4][8];
    #pragma unroll
    for (int i = 0; i < 4; i++) {
        m_i[i] = -INFINITY; l_i[i] = 0.f;
        #pragma unroll
        for (int j = 0; j < 8; j++) acc_o[i][j] = 0.f;
    }

    const size_t kvbase0 = (size_t)b*SS*DD;

    for (int kt = 0; kt < SS/32; kt++) {
        __syncthreads();
        const size_t kvb = kvbase0 + (size_t)kt*32*DD;
        for (int i = tid; i < 32*128; i += 256) {
            int r = i >> 7, d = i & 127;
            Ks[r*132 + d] = Kg[kvb + i];
            Vs[r*132 + d] = Vg[kvb + i];
        }
        __syncthreads();

        float sa[4][2];
        #pragma unroll
        for (int i = 0; i < 4; i++) { sa[i][0] = 0.f; sa[i][1] = 0.f; }

        #pragma unroll 8
        for (int d = 0; d < 128; d += 4) {
            float4 qv[4], kv[2];
            #pragma unroll
            for (int i = 0; i < 4; i++) qv[i] = *(const float4*)&Qs[(ty*4+i)*132 + d];
            #pragma unroll
            for (int j = 0; j < 2; j++) kv[j] = *(const float4*)&Ks[(tx*2+j)*132 + d];
            #pragma unroll
            for (int i = 0; i < 4; i++)
                #pragma unroll
                for (int j = 0; j < 2; j++)
                    sa[i][j] += qv[i].x*kv[j].x + qv[i].y*kv[j].y
                              + qv[i].z*kv[j].z + qv[i].w*kv[j].w;
        }

        #pragma unroll
        for (int i = 0; i < 4; i++) {
            float tmax = fmaxf(sa[i][0], sa[i][1]);
            #pragma unroll
            for (int off = 8; off >= 1; off >>= 1)
                tmax = fmaxf(tmax, __shfl_xor_sync(0xffffffffu, tmax, off, 16));
            float mnew  = fmaxf(m_i[i], tmax);
            float alpha = __expf(m_i[i] - mnew);
            float rsum;
            sa[i][0] = __expf(sa[i][0] - mnew);
            sa[i][1] = __expf(sa[i][1] - mnew);
            rsum = sa[i][0] + sa[i][1];
            #pragma unroll
            for (int off = 8; off >= 1; off >>= 1)
                rsum += __shfl_xor_sync(0xffffffffu, rsum, off, 16);
            l_i[i] = l_i[i]*alpha + rsum;
            m_i[i] = mnew;
            #pragma unroll
            for (int j = 0; j < 8; j++) acc_o[i][j] *= alpha;
            *(float2*)&Ps[(ty*4+i)*36 + tx*2] = make_float2(sa[i][0], sa[i][1]);
        }
        __syncthreads();

        #pragma unroll 2
        for (int kv4 = 0; kv4 < 32; kv4 += 4) {
            float4 pv[4];
            #pragma unroll
            for (int i = 0; i < 4; i++) pv[i] = *(const float4*)&Ps[(ty*4+i)*36 + kv4];
            #pragma unroll
            for (int u = 0; u < 4; u++) {
                float4 v0 = *(const float4*)&Vs[(kv4+u)*132 + tx*8];
                float4 v1 = *(const float4*)&Vs[(kv4+u)*132 + tx*8 + 4];
                #pragma unroll
                for (int i = 0; i < 4; i++) {
                    float p = (u == 0) ? pv[i].x : (u == 1) ? pv[i].y
                            : (u == 2) ? pv[i].z : pv[i].w;
                    acc_o[i][0] += p*v0.x; acc_o[i][1] += p*v0.y;
                    acc_o[i][2] += p*v0.z; acc_o[i][3] += p*v0.w;
                    acc_o[i][4] += p*v1.x; acc_o[i][5] += p*v1.y;
                    acc_o[i][6] += p*v1.z; acc_o[i][7] += p*v1.w;
                }
            }
        }
    }

    __syncthreads();
    #pragma unroll
    for (int i = 0; i < 4; i++) {
        float inv = 1.f / l_i[i];
        #pragma unroll
        for (int j = 0; j < 8; j++) acc_o[i][j] *= inv;
        int r = ty*4 + i;
        *(float4*)&Qs[r*132 + tx*8]     = make_float4(acc_o[i][0], acc_o[i][1], acc_o[i][2], acc_o[i][3]);
        *(float4*)&Qs[r*132 + tx*8 + 4] = make_float4(acc_o[i][4], acc_o[i][5], acc_o[i][6], acc_o[i][7]);
    }
    __syncthreads();

    const size_t obase = (size_t)b*SS*HH;
    for (int i = tid; i < 64*128; i += 256) {
        int d = i >> 6;
        int s = i & 63;
        size_t row = (size_t)h*64 + (d >> 1);
        size_t col = (size_t)(d & 1)*2048 + q0 + s;
        Outp[obase + row*HH + col] = Qs[s*132 + d];
    }
}

// ---------------------------------------------------------------------------
extern "C" void kernel_launch(void* const* d_in, const int* in_sizes, int n_in,
                              void* d_out, int out_size)
{
    const float* X  = (const float*)d_in[0];
    const float* Wq = (const float*)d_in[1];
    const float* bq = (const float*)d_in[2];
    const float* Wk = (const float*)d_in[3];
    const float* bk = (const float*)d_in[4];
    const float* Wv = (const float*)d_in[5];
    const float* bv = (const float*)d_in[6];
    const float* Wo = (const float*)d_in[7];
    const float* bo = (const float*)d_in[8];
    float* out = (float*)d_out;

    float *Qp, *Kp, *Vp, *Ap, *Pp, *Xs, *Wsp;
    cudaGetSymbolAddress((void**)&Qp, g_Q);
    cudaGetSymbolAddress((void**)&Kp, g_K);
    cudaGetSymbolAddress((void**)&Vp, g_V);
    cudaGetSymbolAddress((void**)&Ap, g_attn);
    cudaGetSymbolAddress((void**)&Pp, g_part);
    cudaGetSymbolAddress((void**)&Xs, g_Asplit);
    cudaGetSymbolAddress((void**)&Wsp, g_Wsplit);

    cudaFuncSetAttribute(gemm_tf32_mma,
                         cudaFuncAttributeMaxDynamicSharedMemorySize, GEMM_SMEM_BYTES);
    cudaFuncSetAttribute(mqa_attn_kernel,
                         cudaFuncAttributeMaxDynamicSharedMemorySize,
                         ATTN_SMEM_FLOATS * (int)sizeof(float));

    const int nX2 = MTOT*HH/2, nWqo2 = HH*HH/2, nWkv2 = DD*HH/2;

    // 0) Pre-split X and Wq
    split_pack<<<(nX2 + 255)/256, 256>>>(X, Xs, nX2);
    split_pack<<<(nWqo2 + 255)/256, 256>>>(Wq, Wsp, nWqo2);

    // 1) Q projection (full K)
    gemm_tf32_mma<<<dim3(HH/128, MTOT/128, 1), 256, GEMM_SMEM_BYTES>>>(
        Xs, Wsp, bq, Qp, MTOT, HH, HH, HH);

    // 2) K projection (split-K=4 -> partials -> reduce+bias)
    split_pack<<<(nWkv2 + 255)/256, 256>>>(Wk, Wsp, nWkv2);
    gemm_tf32_mma<<<dim3(DD/128, MTOT/128, 4), 256, GEMM_SMEM_BYTES>>>(
        Xs, Wsp, nullptr, Pp, MTOT, DD, HH, HH/4);
    reduce4_bias<<<(MTOT*DD + 255)/256, 256>>>(Pp, bk, Kp, MTOT*DD, DD);

    // 3) V projection (split-K=4)
    split_pack<<<(nWkv2 + 255)/256, 256>>>(Wv, Wsp, nWkv2);
    gemm_tf32_mma<<<dim3(DD/128, MTOT/128, 4), 256, GEMM_SMEM_BYTES>>>(
        Xs, Wsp, nullptr, Pp, MTOT, DD, HH, HH/4);
    reduce4_bias<<<(MTOT*DD + 255)/256, 256>>>(Pp, bv, Vp, MTOT*DD, DD);

    // 4) Fused attention (fp32, BKV=32, 2 CTAs/SM) -> scrambled layout
    mqa_attn_kernel<<<dim3(SS/64, NHEAD, BB), 256,
                      ATTN_SMEM_FLOATS * sizeof(float)>>>(Qp, Kp, Vp, Ap);

    // 5) O projection: split attn output (reuse Xs) and Wo, then GEMM
    split_pack<<<(nX2 + 255)/256, 256>>>(Ap, Xs, nX2);
    split_pack<<<(nWqo2 + 255)/256, 256>>>(Wo, Wsp, nWqo2);
    gemm_tf32_mma<<<dim3(HH/128, MTOT/128, 1), 256, GEMM_SMEM_BYTES>>>(
        Xs, Wsp, bo, out, MTOT, HH, HH, HH);
}

// round 12
// speedup vs baseline: 1.5107x; 1.4380x over previous
#include <cuda_runtime.h>
#include <cuda_bf16.h>
#include <cstdint>
#include <math.h>

// Problem constants
#define BB    2
#define SS    2048
#define HH    4096
#define NHEAD 32
#define DD    128
#define MTOT  (BB*SS)

// Scratch (no cudaMalloc allowed)
__device__ float g_Q[(size_t)BB*SS*HH];        // 64 MB
__device__ float g_K[(size_t)BB*SS*DD];        // 2 MB
__device__ float g_V[(size_t)BB*SS*DD];        // 2 MB
__device__ float g_attn[(size_t)BB*SS*HH];     // 64 MB (scrambled layout)
__device__ float g_part[(size_t)4*MTOT*DD];    // 8 MB split-K partials
__device__ __nv_bfloat16 g_Asplit[(size_t)2*MTOT*HH]; // 67 MB: hi plane, then lo plane
__device__ __nv_bfloat16 g_Wsplit[(size_t)2*HH*HH];   // 67 MB: hi plane, then lo plane

// ===========================================================================
// Helpers
// ===========================================================================
__device__ __forceinline__ uint32_t smem_u32(const void* p) {
    uint32_t a;
    asm("{ .reg .u64 t; cvta.to.shared.u64 t, %1; cvt.u32.u64 %0, t; }" : "=r"(a) : "l"(p));
    return a;
}
__device__ __forceinline__ void cp_async16(uint32_t dst, const void* src) {
    asm volatile("cp.async.cg.shared.global [%0], [%1], 16;" :: "r"(dst), "l"(src));
}
__device__ __forceinline__ void ldsm_x4(uint32_t& r0, uint32_t& r1, uint32_t& r2,
                                        uint32_t& r3, uint32_t addr) {
    asm volatile("ldmatrix.sync.aligned.m8n8.x4.shared.b16 {%0,%1,%2,%3}, [%4];"
                 : "=r"(r0), "=r"(r1), "=r"(r2), "=r"(r3) : "r"(addr));
}
// bf16 mma.sync: D(16x8) += A(16x16) @ B(8x16)^T, row.col, fp32 accum
__device__ __forceinline__ void mma_bf16(float* d, const uint32_t* a, const uint32_t* b) {
    asm volatile(
        "mma.sync.aligned.m16n8k16.row.col.f32.bf16.bf16.f32 "
        "{%0,%1,%2,%3}, {%4,%5,%6,%7}, {%8,%9}, {%0,%1,%2,%3};"
        : "+f"(d[0]), "+f"(d[1]), "+f"(d[2]), "+f"(d[3])
        : "r"(a[0]), "r"(a[1]), "r"(a[2]), "r"(a[3]), "r"(b[0]), "r"(b[1]));
}

__device__ __forceinline__ uint32_t pk2(__nv_bfloat16 a, __nv_bfloat16 b) {
    return (uint32_t)__bfloat16_as_ushort(a) | ((uint32_t)__bfloat16_as_ushort(b) << 16);
}
__device__ __forceinline__ void spl(float v, __nv_bfloat16& h, __nv_bfloat16& l) {
    h = __float2bfloat16(v);
    l = __float2bfloat16(v - __bfloat162float(h));
}

// ===========================================================================
// Pre-pass: split fp32 array into two bf16 planes (hi, lo). 8 elems/thread.
// ===========================================================================
__global__ void __launch_bounds__(256)
split_bf16(const float* __restrict__ in, __nv_bfloat16* __restrict__ hi,
           __nv_bfloat16* __restrict__ lo, int n8)
{
    int i = blockIdx.x * 256 + threadIdx.x;
    if (i < n8) {
        const float4* p = (const float4*)in;
        float4 a = p[2*i], b = p[2*i+1];
        __nv_bfloat16 h[8], l[8];
        spl(a.x, h[0], l[0]); spl(a.y, h[1], l[1]);
        spl(a.z, h[2], l[2]); spl(a.w, h[3], l[3]);
        spl(b.x, h[4], l[4]); spl(b.y, h[5], l[5]);
        spl(b.z, h[6], l[6]); spl(b.w, h[7], l[7]);
        uint4 H, L;
        H.x = pk2(h[0], h[1]); H.y = pk2(h[2], h[3]);
        H.z = pk2(h[4], h[5]); H.w = pk2(h[6], h[7]);
        L.x = pk2(l[0], l[1]); L.y = pk2(l[2], l[3]);
        L.z = pk2(l[4], l[5]); L.w = pk2(l[6], l[7]);
        ((uint4*)hi)[i] = H;
        ((uint4*)lo)[i] = L;
    }
}

// ===========================================================================
// bf16x3 tensor-core GEMM:  C[M,N] = A[M,K] @ W[N,K]^T (+ bias when gridDim.z==1)
// A, W pre-split into bf16 hi/lo planes. CTA 128x128, K-chunk 32, cp.async
// double-buffered. a*b ~= ah*bh + ah*bl + al*bh (3 bf16 MMAs per k16).
// Smem: 4 tiles/stage (Ah, Al, Wh, Wl), each 128 rows x 32 bf16, row stride
// 80 B (16B-aligned, ldmatrix-conflict-free: bank starts (20r)%32 distinct).
// 8 warps (2x4), warp tile 64x32. Inner loop: ldmatrix.x4 + mma only.
// Split-K: blockIdx.z picks K segment of kLen; partials to C + z*M*N.
// ===========================================================================
#define ROWB 80
#define TILE_BYTES (128*ROWB)            // 10240
#define STAGE_BYTES (4*TILE_BYTES)       // 40960
#define GEMM_SMEM_BYTES (2*STAGE_BYTES)  // 81920

__global__ void __launch_bounds__(256, 2)
gemm_bf16x3(const __nv_bfloat16* __restrict__ Ah, const __nv_bfloat16* __restrict__ Al,
            const __nv_bfloat16* __restrict__ Wh, const __nv_bfloat16* __restrict__ Wl,
            const float* __restrict__ bias, float* __restrict__ C,
            int M, int N, int Kdim, int kLen)
{
    extern __shared__ char smem[];
    const uint32_t smem_base = smem_u32(smem);

    const int tid = threadIdx.x;
    const int wid = tid >> 5;
    const int lane = tid & 31;
    const int g = lane >> 2;
    const int t = lane & 3;
    const int wm = wid & 1;
    const int wn = wid >> 1;
    const int m0 = blockIdx.y * 128;
    const int n0 = blockIdx.x * 128;
    const int kOff = blockIdx.z * kLen;

    float acc[4][4][4];
    #pragma unroll
    for (int i = 0; i < 4; i++)
        #pragma unroll
        for (int j = 0; j < 4; j++)
            #pragma unroll
            for (int r = 0; r < 4; r++) acc[i][j][r] = 0.f;

    const int nch = kLen >> 5;

    // copy indices: thread -> (row, 16B granule); 2 passes cover 128 rows
    const int crow = tid >> 2;       // 0..63
    const int ccol = tid & 3;        // 0..3  (x8 bf16)

    // ldmatrix per-lane address components
    const int a_row_l = (lane & 7) + ((lane >> 3) & 1) * 8;  // 0..15
    const int a_k16   = (lane >> 4) * 16;
    const int b_row_l = (lane >> 4) * 8 + (lane & 7);        // 0..15
    const int b_k16   = ((lane >> 3) & 1) * 16;

    auto stage = [&](int cidx, uint32_t dstbase) {
        const size_t kb = (size_t)kOff + (size_t)cidx * 32 + ccol * 8;
        #pragma unroll
        for (int p = 0; p < 2; p++) {
            int r = crow + 64 * p;
            uint32_t d = dstbase + (uint32_t)(r * ROWB + ccol * 16);
            cp_async16(d,                 Ah + (size_t)(m0 + r) * Kdim + kb);
            cp_async16(d +   TILE_BYTES,  Al + (size_t)(m0 + r) * Kdim + kb);
            cp_async16(d + 2*TILE_BYTES,  Wh + (size_t)(n0 + r) * Kdim + kb);
            cp_async16(d + 3*TILE_BYTES,  Wl + (size_t)(n0 + r) * Kdim + kb);
        }
    };

    // prologue
    stage(0, smem_base);
    asm volatile("cp.async.commit_group;" ::: "memory");

    for (int c = 0; c < nch; c++) {
        if (c + 1 < nch) {
            stage(c + 1, smem_base + (uint32_t)((c + 1) & 1) * STAGE_BYTES);
            asm volatile("cp.async.commit_group;" ::: "memory");
            asm volatile("cp.async.wait_group 1;" ::: "memory");
        } else {
            asm volatile("cp.async.wait_group 0;" ::: "memory");
        }
        __syncthreads();

        const uint32_t sb = smem_base + (uint32_t)(c & 1) * STAGE_BYTES;
        const uint32_t aBase = sb + (uint32_t)((wm * 64 + a_row_l) * ROWB + a_k16);
        const uint32_t bBase = sb + 2*TILE_BYTES
                             + (uint32_t)((wn * 32 + b_row_l) * ROWB + b_k16);

        #pragma unroll
        for (int ks = 0; ks < 2; ks++) {
            uint32_t bh[4][2], bl[4][2];
            #pragma unroll
            for (int tnp = 0; tnp < 2; tnp++) {
                uint32_t ad = bBase + tnp * (16 * ROWB) + ks * 32;
                ldsm_x4(bh[2*tnp][0], bh[2*tnp][1], bh[2*tnp+1][0], bh[2*tnp+1][1], ad);
                ldsm_x4(bl[2*tnp][0], bl[2*tnp][1], bl[2*tnp+1][0], bl[2*tnp+1][1],
                        ad + TILE_BYTES);
            }
            #pragma unroll
            for (int mh = 0; mh < 2; mh++) {
                uint32_t ah[2][4], al[2][4];
                #pragma unroll
                for (int q = 0; q < 2; q++) {
                    uint32_t ad = aBase + (mh * 2 + q) * (16 * ROWB) + ks * 32;
                    ldsm_x4(ah[q][0], ah[q][1], ah[q][2], ah[q][3], ad);
                    ldsm_x4(al[q][0], al[q][1], al[q][2], al[q][3], ad + TILE_BYTES);
                }
                #pragma unroll
                for (int q = 0; q < 2; q++)
                    #pragma unroll
                    for (int tn = 0; tn < 4; tn++) {
                        float* d = acc[mh * 2 + q][tn];
                        mma_bf16(d, al[q], bh[tn]);
                        mma_bf16(d, ah[q], bl[tn]);
                        mma_bf16(d, ah[q], bh[tn]);
                    }
            }
        }
        __syncthreads();
    }

    // Epilogue
    const bool full = (gridDim.z == 1);
    float* Cout = C + (full ? (size_t)0 : (size_t)blockIdx.z * M * N);
    #pragma unroll
    for (int mt = 0; mt < 4; mt++) {
        int row = m0 + wm * 64 + mt * 16 + g;
        #pragma unroll
        for (int tn = 0; tn < 4; tn++) {
            int col = n0 + wn * 32 + tn * 8 + t * 2;
            float bx = 0.f, by = 0.f;
            if (full) { float2 bv = *(const float2*)(bias + col); bx = bv.x; by = bv.y; }
            float2 v0, v1;
            v0.x = acc[mt][tn][0] + bx; v0.y = acc[mt][tn][1] + by;
            v1.x = acc[mt][tn][2] + bx; v1.y = acc[mt][tn][3] + by;
            *(float2*)(Cout + (size_t)row * N + col) = v0;
            *(float2*)(Cout + (size_t)(row + 8) * N + col) = v1;
        }
    }
}

// Deterministic split-K reduce: out[i] = sum_{s<4} part[s][i] + bias[i % N]
__global__ void __launch_bounds__(256)
reduce4_bias(const float* __restrict__ part, const float* __restrict__ bias,
             float* __restrict__ out, int MN, int N)
{
    int i = blockIdx.x * 256 + threadIdx.x;
    if (i < MN) {
        float v = (part[i] + part[(size_t)MN + i])
                + (part[(size_t)2*MN + i] + part[(size_t)3*MN + i]);
        out[i] = v + bias[i & (N - 1)];
    }
}

// ---------------------------------------------------------------------------
// Fused MQA flash attention, fp32. BQ=64, BKV=32, 2 CTAs/SM. (validated R4/R5)
// Epilogue stores scrambled layout: A[b, h*64 + d/2, (d&1)*2048 + q0 + s]
// ---------------------------------------------------------------------------
#define ATTN_SMEM_FLOATS (8448 + 4224 + 4224 + 64*36)   // 76800 B

__global__ void __launch_bounds__(256, 2)
mqa_attn_kernel(const float* __restrict__ Q, const float* __restrict__ Kg,
                const float* __restrict__ Vg, float* __restrict__ Outp)
{
    extern __shared__ float sm[];
    float* Qs = sm;             // [64][132]
    float* Ks = sm + 8448;      // [32][132]
    float* Vs = sm + 12672;     // [32][132]
    float* Ps = sm + 16896;     // [64][36]

    const int tid = threadIdx.x;
    const int qt  = blockIdx.x;
    const int h   = blockIdx.y;
    const int b   = blockIdx.z;
    const int tx  = tid & 15;
    const int ty  = tid >> 4;

    const float scale = 0.08838834764831845f;
    const int q0 = qt * 64;

    const size_t qbase = ((size_t)b*SS + q0)*HH + (size_t)h*DD;
    for (int i = tid; i < 64*128; i += 256) {
        int r = i >> 7, d = i & 127;
        Qs[r*132 + d] = Q[qbase + (size_t)r*HH + d] * scale;
    }

    float m_i[4], l_i[4], acc_o[4][8];
    #pragma unroll
    for (int i = 0; i < 4; i++) {
        m_i[i] = -INFINITY; l_i[i] = 0.f;
        #pragma unroll
        for (int j = 0; j < 8; j++) acc_o[i][j] = 0.f;
    }

    const size_t kvbase0 = (size_t)b*SS*DD;

    for (int kt = 0; kt < SS/32; kt++) {
        __syncthreads();
        const size_t kvb = kvbase0 + (size_t)kt*32*DD;
        for (int i = tid; i < 32*128; i += 256) {
            int r = i >> 7, d = i & 127;
            Ks[r*132 + d] = Kg[kvb + i];
            Vs[r*132 + d] = Vg[kvb + i];
        }
        __syncthreads();

        float sa[4][2];
        #pragma unroll
        for (int i = 0; i < 4; i++) { sa[i][0] = 0.f; sa[i][1] = 0.f; }

        #pragma unroll 8
        for (int d = 0; d < 128; d += 4) {
            float4 qv[4], kv[2];
            #pragma unroll
            for (int i = 0; i < 4; i++) qv[i] = *(const float4*)&Qs[(ty*4+i)*132 + d];
            #pragma unroll
            for (int j = 0; j < 2; j++) kv[j] = *(const float4*)&Ks[(tx*2+j)*132 + d];
            #pragma unroll
            for (int i = 0; i < 4; i++)
                #pragma unroll
                for (int j = 0; j < 2; j++)
                    sa[i][j] += qv[i].x*kv[j].x + qv[i].y*kv[j].y
                              + qv[i].z*kv[j].z + qv[i].w*kv[j].w;
        }

        #pragma unroll
        for (int i = 0; i < 4; i++) {
            float tmax = fmaxf(sa[i][0], sa[i][1]);
            #pragma unroll
            for (int off = 8; off >= 1; off >>= 1)
                tmax = fmaxf(tmax, __shfl_xor_sync(0xffffffffu, tmax, off, 16));
            float mnew  = fmaxf(m_i[i], tmax);
            float alpha = __expf(m_i[i] - mnew);
            float rsum;
            sa[i][0] = __expf(sa[i][0] - mnew);
            sa[i][1] = __expf(sa[i][1] - mnew);
            rsum = sa[i][0] + sa[i][1];
            #pragma unroll
            for (int off = 8; off >= 1; off >>= 1)
                rsum += __shfl_xor_sync(0xffffffffu, rsum, off, 16);
            l_i[i] = l_i[i]*alpha + rsum;
            m_i[i] = mnew;
            #pragma unroll
            for (int j = 0; j < 8; j++) acc_o[i][j] *= alpha;
            *(float2*)&Ps[(ty*4+i)*36 + tx*2] = make_float2(sa[i][0], sa[i][1]);
        }
        __syncthreads();

        #pragma unroll 2
        for (int kv4 = 0; kv4 < 32; kv4 += 4) {
            float4 pv[4];
            #pragma unroll
            for (int i = 0; i < 4; i++) pv[i] = *(const float4*)&Ps[(ty*4+i)*36 + kv4];
            #pragma unroll
            for (int u = 0; u < 4; u++) {
                float4 v0 = *(const float4*)&Vs[(kv4+u)*132 + tx*8];
                float4 v1 = *(const float4*)&Vs[(kv4+u)*132 + tx*8 + 4];
                #pragma unroll
                for (int i = 0; i < 4; i++) {
                    float p = (u == 0) ? pv[i].x : (u == 1) ? pv[i].y
                            : (u == 2) ? pv[i].z : pv[i].w;
                    acc_o[i][0] += p*v0.x; acc_o[i][1] += p*v0.y;
                    acc_o[i][2] += p*v0.z; acc_o[i][3] += p*v0.w;
                    acc_o[i][4] += p*v1.x; acc_o[i][5] += p*v1.y;
                    acc_o[i][6] += p*v1.z; acc_o[i][7] += p*v1.w;
                }
            }
        }
    }

    __syncthreads();
    #pragma unroll
    for (int i = 0; i < 4; i++) {
        float inv = 1.f / l_i[i];
        #pragma unroll
        for (int j = 0; j < 8; j++) acc_o[i][j] *= inv;
        int r = ty*4 + i;
        *(float4*)&Qs[r*132 + tx*8]     = make_float4(acc_o[i][0], acc_o[i][1], acc_o[i][2], acc_o[i][3]);
        *(float4*)&Qs[r*132 + tx*8 + 4] = make_float4(acc_o[i][4], acc_o[i][5], acc_o[i][6], acc_o[i][7]);
    }
    __syncthreads();

    const size_t obase = (size_t)b*SS*HH;
    for (int i = tid; i < 64*128; i += 256) {
        int d = i >> 6;
        int s = i & 63;
        size_t row = (size_t)h*64 + (d >> 1);
        size_t col = (size_t)(d & 1)*2048 + q0 + s;
        Outp[obase + row*HH + col] = Qs[s*132 + d];
    }
}

// ---------------------------------------------------------------------------
extern "C" void kernel_launch(void* const* d_in, const int* in_sizes, int n_in,
                              void* d_out, int out_size)
{
    const float* X  = (const float*)d_in[0];
    const float* Wq = (const float*)d_in[1];
    const float* bq = (const float*)d_in[2];
    const float* Wk = (const float*)d_in[3];
    const float* bk = (const float*)d_in[4];
    const float* Wv = (const float*)d_in[5];
    const float* bv = (const float*)d_in[6];
    const float* Wo = (const float*)d_in[7];
    const float* bo = (const float*)d_in[8];
    float* out = (float*)d_out;

    float *Qp, *Kp, *Vp, *Ap, *Pp;
    __nv_bfloat16 *Xs, *Ws;
    cudaGetSymbolAddress((void**)&Qp, g_Q);
    cudaGetSymbolAddress((void**)&Kp, g_K);
    cudaGetSymbolAddress((void**)&Vp, g_V);
    cudaGetSymbolAddress((void**)&Ap, g_attn);
    cudaGetSymbolAddress((void**)&Pp, g_part);
    cudaGetSymbolAddress((void**)&Xs, g_Asplit);
    cudaGetSymbolAddress((void**)&Ws, g_Wsplit);

    __nv_bfloat16* Xh = Xs;                       // hi plane
    __nv_bfloat16* Xl = Xs + (size_t)MTOT * HH;   // lo plane
    __nv_bfloat16* Wh = Ws;
    __nv_bfloat16* Wl = Ws + (size_t)HH * HH;

    cudaFuncSetAttribute(gemm_bf16x3,
                         cudaFuncAttributeMaxDynamicSharedMemorySize, GEMM_SMEM_BYTES);
    cudaFuncSetAttribute(mqa_attn_kernel,
                         cudaFuncAttributeMaxDynamicSharedMemorySize,
                         ATTN_SMEM_FLOATS * (int)sizeof(float));

    const int nX8 = MTOT*HH/8, nWqo8 = HH*HH/8, nWkv8 = DD*HH/8;

    // 0) split X and Wq into bf16 planes
    split_bf16<<<(nX8 + 255)/256, 256>>>(X, Xh, Xl, nX8);
    split_bf16<<<(nWqo8 + 255)/256, 256>>>(Wq, Wh, Wl, nWqo8);

    // 1) Q projection (full K)
    gemm_bf16x3<<<dim3(HH/128, MTOT/128, 1), 256, GEMM_SMEM_BYTES>>>(
        Xh, Xl, Wh, Wl, bq, Qp, MTOT, HH, HH, HH);

    // 2) K projection (split-K=4 -> partials -> reduce+bias)
    split_bf16<<<(nWkv8 + 255)/256, 256>>>(Wk, Wh, Wl, nWkv8);
    gemm_bf16x3<<<dim3(DD/128, MTOT/128, 4), 256, GEMM_SMEM_BYTES>>>(
        Xh, Xl, Wh, Wl, nullptr, Pp, MTOT, DD, HH, HH/4);
    reduce4_bias<<<(MTOT*DD + 255)/256, 256>>>(Pp, bk, Kp, MTOT*DD, DD);

    // 3) V projection (split-K=4)
    split_bf16<<<(nWkv8 + 255)/256, 256>>>(Wv, Wh, Wl, nWkv8);
    gemm_bf16x3<<<dim3(DD/128, MTOT/128, 4), 256, GEMM_SMEM_BYTES>>>(
        Xh, Xl, Wh, Wl, nullptr, Pp, MTOT, DD, HH, HH/4);
    reduce4_bias<<<(MTOT*DD + 255)/256, 256>>>(Pp, bv, Vp, MTOT*DD, DD);

    // 4) Fused attention (fp32) -> scrambled layout
    mqa_attn_kernel<<<dim3(SS/64, NHEAD, BB), 256,
                      ATTN_SMEM_FLOATS * sizeof(float)>>>(Qp, Kp, Vp, Ap);

    // 5) O projection: split attn output (reuse Xs) and Wo, then GEMM
    split_bf16<<<(nX8 + 255)/256, 256>>>(Ap, Xh, Xl, nX8);
    split_bf16<<<(nWqo8 + 255)/256, 256>>>(Wo, Wh, Wl, nWqo8);
    gemm_bf16x3<<<dim3(HH/128, MTOT/128, 1), 256, GEMM_SMEM_BYTES>>>(
        Xh, Xl, Wh, Wl, bo, out, MTOT, HH, HH, HH);
}

// round 13
// speedup vs baseline: 3.5156x; 2.3271x over previous
#include <cuda_runtime.h>
#include <cuda_bf16.h>
#include <cstdint>
#include <math.h>

// Problem constants
#define BB    2
#define SS    2048
#define HH    4096
#define NHEAD 32
#define DD    128
#define MTOT  (BB*SS)

// Scratch (no cudaMalloc allowed)
__device__ float g_Q[(size_t)BB*SS*HH];        // 64 MB
__device__ float g_K[(size_t)BB*SS*DD];        // 2 MB
__device__ float g_V[(size_t)BB*SS*DD];        // 2 MB
__device__ float g_attn[(size_t)BB*SS*HH];     // 64 MB (scrambled layout)
__device__ float g_part[(size_t)4*MTOT*DD];    // 8 MB split-K partials
__device__ __nv_bfloat16 g_Asplit[(size_t)2*MTOT*HH]; // X/Q/attn splits (hi plane, lo plane)
__device__ __nv_bfloat16 g_Wsplit[(size_t)2*HH*HH];   // W splits (sequential reuse)
__device__ __nv_bfloat16 g_Ks[(size_t)2*MTOT*DD];     // K split planes
__device__ __nv_bfloat16 g_Vs[(size_t)2*MTOT*DD];     // V split planes

// ===========================================================================
// Helpers
// ===========================================================================
__device__ __forceinline__ uint32_t smem_u32(const void* p) {
    uint32_t a;
    asm("{ .reg .u64 t; cvta.to.shared.u64 t, %1; cvt.u32.u64 %0, t; }" : "=r"(a) : "l"(p));
    return a;
}
__device__ __forceinline__ void cp_async16(uint32_t dst, const void* src) {
    asm volatile("cp.async.cg.shared.global [%0], [%1], 16;" :: "r"(dst), "l"(src));
}
__device__ __forceinline__ void ldsm_x4(uint32_t& r0, uint32_t& r1, uint32_t& r2,
                                        uint32_t& r3, uint32_t addr) {
    asm volatile("ldmatrix.sync.aligned.m8n8.x4.shared.b16 {%0,%1,%2,%3}, [%4];"
                 : "=r"(r0), "=r"(r1), "=r"(r2), "=r"(r3) : "r"(addr));
}
__device__ __forceinline__ void ldsm_x4_t(uint32_t& r0, uint32_t& r1, uint32_t& r2,
                                          uint32_t& r3, uint32_t addr) {
    asm volatile("ldmatrix.sync.aligned.m8n8.x4.trans.shared.b16 {%0,%1,%2,%3}, [%4];"
                 : "=r"(r0), "=r"(r1), "=r"(r2), "=r"(r3) : "r"(addr));
}
// bf16 mma.sync: D(16x8) += A(16x16) @ B(8x16)^T, row.col, fp32 accum
__device__ __forceinline__ void mma_bf16(float* d, const uint32_t* a, const uint32_t* b) {
    asm volatile(
        "mma.sync.aligned.m16n8k16.row.col.f32.bf16.bf16.f32 "
        "{%0,%1,%2,%3}, {%4,%5,%6,%7}, {%8,%9}, {%0,%1,%2,%3};"
        : "+f"(d[0]), "+f"(d[1]), "+f"(d[2]), "+f"(d[3])
        : "r"(a[0]), "r"(a[1]), "r"(a[2]), "r"(a[3]), "r"(b[0]), "r"(b[1]));
}

__device__ __forceinline__ uint32_t pk2(__nv_bfloat16 a, __nv_bfloat16 b) {
    return (uint32_t)__bfloat16_as_ushort(a) | ((uint32_t)__bfloat16_as_ushort(b) << 16);
}
__device__ __forceinline__ void spl(float v, __nv_bfloat16& h, __nv_bfloat16& l) {
    h = __float2bfloat16(v);
    l = __float2bfloat16(v - __bfloat162float(h));
}

// ===========================================================================
// Pre-pass: split (scale * fp32) into two bf16 planes (hi, lo). 8 elems/thread.
// ===========================================================================
__global__ void __launch_bounds__(256)
split_bf16(const float* __restrict__ in, __nv_bfloat16* __restrict__ hi,
           __nv_bfloat16* __restrict__ lo, int n8, float scale)
{
    int i = blockIdx.x * 256 + threadIdx.x;
    if (i < n8) {
        const float4* p = (const float4*)in;
        float4 a = p[2*i], b = p[2*i+1];
        __nv_bfloat16 h[8], l[8];
        spl(a.x*scale, h[0], l[0]); spl(a.y*scale, h[1], l[1]);
        spl(a.z*scale, h[2], l[2]); spl(a.w*scale, h[3], l[3]);
        spl(b.x*scale, h[4], l[4]); spl(b.y*scale, h[5], l[5]);
        spl(b.z*scale, h[6], l[6]); spl(b.w*scale, h[7], l[7]);
        uint4 H, L;
        H.x = pk2(h[0], h[1]); H.y = pk2(h[2], h[3]);
        H.z = pk2(h[4], h[5]); H.w = pk2(h[6], h[7]);
        L.x = pk2(l[0], l[1]); L.y = pk2(l[2], l[3]);
        L.z = pk2(l[4], l[5]); L.w = pk2(l[6], l[7]);
        ((uint4*)hi)[i] = H;
        ((uint4*)lo)[i] = L;
    }
}

// ===========================================================================
// bf16x3 tensor-core GEMM (validated R12 — unchanged)
// ===========================================================================
#define ROWB 80
#define TILE_BYTES (128*ROWB)
#define STAGE_BYTES (4*TILE_BYTES)
#define GEMM_SMEM_BYTES (2*STAGE_BYTES)

__global__ void __launch_bounds__(256, 2)
gemm_bf16x3(const __nv_bfloat16* __restrict__ Ah, const __nv_bfloat16* __restrict__ Al,
            const __nv_bfloat16* __restrict__ Wh, const __nv_bfloat16* __restrict__ Wl,
            const float* __restrict__ bias, float* __restrict__ C,
            int M, int N, int Kdim, int kLen)
{
    extern __shared__ char smem[];
    const uint32_t smem_base = smem_u32(smem);

    const int tid = threadIdx.x;
    const int wid = tid >> 5;
    const int lane = tid & 31;
    const int g = lane >> 2;
    const int t = lane & 3;
    const int wm = wid & 1;
    const int wn = wid >> 1;
    const int m0 = blockIdx.y * 128;
    const int n0 = blockIdx.x * 128;
    const int kOff = blockIdx.z * kLen;

    float acc[4][4][4];
    #pragma unroll
    for (int i = 0; i < 4; i++)
        #pragma unroll
        for (int j = 0; j < 4; j++)
            #pragma unroll
            for (int r = 0; r < 4; r++) acc[i][j][r] = 0.f;

    const int nch = kLen >> 5;
    const int crow = tid >> 2;
    const int ccol = tid & 3;

    const int a_row_l = (lane & 7) + ((lane >> 3) & 1) * 8;
    const int a_k16   = (lane >> 4) * 16;
    const int b_row_l = (lane >> 4) * 8 + (lane & 7);
    const int b_k16   = ((lane >> 3) & 1) * 16;

    auto stage = [&](int cidx, uint32_t dstbase) {
        const size_t kb = (size_t)kOff + (size_t)cidx * 32 + ccol * 8;
        #pragma unroll
        for (int p = 0; p < 2; p++) {
            int r = crow + 64 * p;
            uint32_t d = dstbase + (uint32_t)(r * ROWB + ccol * 16);
            cp_async16(d,                 Ah + (size_t)(m0 + r) * Kdim + kb);
            cp_async16(d +   TILE_BYTES,  Al + (size_t)(m0 + r) * Kdim + kb);
            cp_async16(d + 2*TILE_BYTES,  Wh + (size_t)(n0 + r) * Kdim + kb);
            cp_async16(d + 3*TILE_BYTES,  Wl + (size_t)(n0 + r) * Kdim + kb);
        }
    };

    stage(0, smem_base);
    asm volatile("cp.async.commit_group;" ::: "memory");

    for (int c = 0; c < nch; c++) {
        if (c + 1 < nch) {
            stage(c + 1, smem_base + (uint32_t)((c + 1) & 1) * STAGE_BYTES);
            asm volatile("cp.async.commit_group;" ::: "memory");
            asm volatile("cp.async.wait_group 1;" ::: "memory");
        } else {
            asm volatile("cp.async.wait_group 0;" ::: "memory");
        }
        __syncthreads();

        const uint32_t sb = smem_base + (uint32_t)(c & 1) * STAGE_BYTES;
        const uint32_t aBase = sb + (uint32_t)((wm * 64 + a_row_l) * ROWB + a_k16);
        const uint32_t bBase = sb + 2*TILE_BYTES
                             + (uint32_t)((wn * 32 + b_row_l) * ROWB + b_k16);

        #pragma unroll
        for (int ks = 0; ks < 2; ks++) {
            uint32_t bh[4][2], bl[4][2];
            #pragma unroll
            for (int tnp = 0; tnp < 2; tnp++) {
                uint32_t ad = bBase + tnp * (16 * ROWB) + ks * 32;
                ldsm_x4(bh[2*tnp][0], bh[2*tnp][1], bh[2*tnp+1][0], bh[2*tnp+1][1], ad);
                ldsm_x4(bl[2*tnp][0], bl[2*tnp][1], bl[2*tnp+1][0], bl[2*tnp+1][1],
                        ad + TILE_BYTES);
            }
            #pragma unroll
            for (int mh = 0; mh < 2; mh++) {
                uint32_t ah[2][4], al[2][4];
                #pragma unroll
                for (int q = 0; q < 2; q++) {
                    uint32_t ad = aBase + (mh * 2 + q) * (16 * ROWB) + ks * 32;
                    ldsm_x4(ah[q][0], ah[q][1], ah[q][2], ah[q][3], ad);
                    ldsm_x4(al[q][0], al[q][1], al[q][2], al[q][3], ad + TILE_BYTES);
                }
                #pragma unroll
                for (int q = 0; q < 2; q++)
                    #pragma unroll
                    for (int tn = 0; tn < 4; tn++) {
                        float* d = acc[mh * 2 + q][tn];
                        mma_bf16(d, al[q], bh[tn]);
                        mma_bf16(d, ah[q], bl[tn]);
                        mma_bf16(d, ah[q], bh[tn]);
                    }
            }
        }
        __syncthreads();
    }

    const bool full = (gridDim.z == 1);
    float* Cout = C + (full ? (size_t)0 : (size_t)blockIdx.z * M * N);
    #pragma unroll
    for (int mt = 0; mt < 4; mt++) {
        int row = m0 + wm * 64 + mt * 16 + g;
        #pragma unroll
        for (int tn = 0; tn < 4; tn++) {
            int col = n0 + wn * 32 + tn * 8 + t * 2;
            float bx = 0.f, by = 0.f;
            if (full) { float2 bv = *(const float2*)(bias + col); bx = bv.x; by = bv.y; }
            float2 v0, v1;
            v0.x = acc[mt][tn][0] + bx; v0.y = acc[mt][tn][1] + by;
            v1.x = acc[mt][tn][2] + bx; v1.y = acc[mt][tn][3] + by;
            *(float2*)(Cout + (size_t)row * N + col) = v0;
            *(float2*)(Cout + (size_t)(row + 8) * N + col) = v1;
        }
    }
}

// Deterministic split-K reduce
__global__ void __launch_bounds__(256)
reduce4_bias(const float* __restrict__ part, const float* __restrict__ bias,
             float* __restrict__ out, int MN, int N)
{
    int i = blockIdx.x * 256 + threadIdx.x;
    if (i < MN) {
        float v = (part[i] + part[(size_t)MN + i])
                + (part[(size_t)2*MN + i] + part[(size_t)3*MN + i]);
        out[i] = v + bias[i & (N - 1)];
    }
}

// ===========================================================================
// bf16x3 MMA flash attention. BQ=64, BKV=64, D=128, 128 threads (4 warps).
// Each warp owns 16 q-rows, full BKV. S and O accumulate via m16n8k16 bf16
// x3 scheme; S C-frags convert in-register to PV A-frags; V via ldmatrix.trans.
// Epilogue stores the reference's scrambled layout.
// ===========================================================================
#define AT_STRIDE 272                    // bytes per 128-bf16 row (+16 pad)
#define AT_TILE  (64*AT_STRIDE)          // 17408
#define AT_SMEM  (6*AT_TILE)             // 104448 -> 2 CTAs/SM

__global__ void __launch_bounds__(128, 2)
mqa_attn_mma(const __nv_bfloat16* __restrict__ Qh, const __nv_bfloat16* __restrict__ Ql,
             const __nv_bfloat16* __restrict__ Kh, const __nv_bfloat16* __restrict__ Kl,
             const __nv_bfloat16* __restrict__ Vh, const __nv_bfloat16* __restrict__ Vl,
             float* __restrict__ Outp)
{
    extern __shared__ char smem[];
    const uint32_t sb = smem_u32(smem);
    const int tid = threadIdx.x;
    const int w = tid >> 5;
    const int lane = tid & 31;
    const int g = lane >> 2, t = lane & 3;
    const int q0 = blockIdx.x * 64;
    const int h = blockIdx.y;
    const int b = blockIdx.z;

    const uint32_t SQh = sb, SQl = sb + AT_TILE, SKh = sb + 2*AT_TILE,
                   SKl = sb + 3*AT_TILE, SVh = sb + 4*AT_TILE, SVl = sb + 5*AT_TILE;

    // Q tiles (hi/lo), loaded once
    {
        const size_t qg = ((size_t)(b*SS + q0))*HH + (size_t)h*DD;
        for (int i = tid; i < 64*16; i += 128) {
            int r = i >> 4, ch = i & 15;
            size_t src = qg + (size_t)r*HH + ch*8;
            uint32_t dst = (uint32_t)(r*AT_STRIDE + ch*16);
            cp_async16(SQh + dst, Qh + src);
            cp_async16(SQl + dst, Ql + src);
        }
        asm volatile("cp.async.commit_group;" ::: "memory");
    }

    float m0 = -INFINITY, m1 = -INFINITY, l0 = 0.f, l1 = 0.f;
    float oacc[16][4];
    #pragma unroll
    for (int j = 0; j < 16; j++)
        #pragma unroll
        for (int r = 0; r < 4; r++) oacc[j][r] = 0.f;

    // fragment lane addresses (validated patterns)
    const uint32_t qa = SQh + (uint32_t)((w*16 + (lane&7) + ((lane>>3)&1)*8)*AT_STRIDE
                                         + ((lane>>4)&1)*16);
    const uint32_t kb = SKh + (uint32_t)(((lane>>4)*8 + (lane&7))*AT_STRIDE
                                         + ((lane>>3)&1)*16);
    const uint32_t va = SVh + (uint32_t)(((lane&7) + ((lane>>3)&1)*8)*AT_STRIDE
                                         + ((lane>>4)&1)*16);

    const size_t kvg0 = (size_t)(b*SS)*DD;

    for (int kt = 0; kt < SS/64; kt++) {
        __syncthreads();
        // stage K/V chunk (hi/lo)
        for (int i = tid; i < 64*16; i += 128) {
            int r = i >> 4, ch = i & 15;
            size_t src = kvg0 + (size_t)(kt*64 + r)*DD + ch*8;
            uint32_t dst = (uint32_t)(r*AT_STRIDE + ch*16);
            cp_async16(SKh + dst, Kh + src);
            cp_async16(SKl + dst, Kl + src);
            cp_async16(SVh + dst, Vh + src);
            cp_async16(SVl + dst, Vl + src);
        }
        asm volatile("cp.async.commit_group;" ::: "memory");
        asm volatile("cp.async.wait_group 0;" ::: "memory");
        __syncthreads();

        // ---- S = Q @ K^T  (x3), per-warp 16x64
        float sacc[8][4];
        #pragma unroll
        for (int j = 0; j < 8; j++)
            #pragma unroll
            for (int r = 0; r < 4; r++) sacc[j][r] = 0.f;

        #pragma unroll
        for (int ks = 0; ks < 8; ks++) {
            uint32_t qh_[4], ql_[4];
            ldsm_x4(qh_[0], qh_[1], qh_[2], qh_[3], qa + ks*32);
            ldsm_x4(ql_[0], ql_[1], ql_[2], ql_[3], qa + AT_TILE + ks*32);
            #pragma unroll
            for (int np = 0; np < 4; np++) {
                uint32_t kh4[4], kl4[4];
                uint32_t ad = kb + np*(16*AT_STRIDE) + ks*32;
                ldsm_x4(kh4[0], kh4[1], kh4[2], kh4[3], ad);
                ldsm_x4(kl4[0], kl4[1], kl4[2], kl4[3], ad + AT_TILE);
                mma_bf16(sacc[2*np],   ql_, &kh4[0]);
                mma_bf16(sacc[2*np],   qh_, &kl4[0]);
                mma_bf16(sacc[2*np],   qh_, &kh4[0]);
                mma_bf16(sacc[2*np+1], ql_, &kh4[2]);
                mma_bf16(sacc[2*np+1], qh_, &kl4[2]);
                mma_bf16(sacc[2*np+1], qh_, &kh4[2]);
            }
        }

        // ---- online softmax (rows g and g+8, warp-private)
        float rx0 = -INFINITY, rx1 = -INFINITY;
        #pragma unroll
        for (int j = 0; j < 8; j++) {
            rx0 = fmaxf(rx0, fmaxf(sacc[j][0], sacc[j][1]));
            rx1 = fmaxf(rx1, fmaxf(sacc[j][2], sacc[j][3]));
        }
        rx0 = fmaxf(rx0, __shfl_xor_sync(0xffffffffu, rx0, 1));
        rx0 = fmaxf(rx0, __shfl_xor_sync(0xffffffffu, rx0, 2));
        rx1 = fmaxf(rx1, __shfl_xor_sync(0xffffffffu, rx1, 1));
        rx1 = fmaxf(rx1, __shfl_xor_sync(0xffffffffu, rx1, 2));
        float mn0 = fmaxf(m0, rx0), mn1 = fmaxf(m1, rx1);
        float a0 = __expf(m0 - mn0), a1 = __expf(m1 - mn1);
        m0 = mn0; m1 = mn1;
        float rs0 = 0.f, rs1 = 0.f;
        #pragma unroll
        for (int j = 0; j < 8; j++) {
            sacc[j][0] = __expf(sacc[j][0] - mn0);
            sacc[j][1] = __expf(sacc[j][1] - mn0);
            sacc[j][2] = __expf(sacc[j][2] - mn1);
            sacc[j][3] = __expf(sacc[j][3] - mn1);
            rs0 += sacc[j][0] + sacc[j][1];
            rs1 += sacc[j][2] + sacc[j][3];
        }
        rs0 += __shfl_xor_sync(0xffffffffu, rs0, 1);
        rs0 += __shfl_xor_sync(0xffffffffu, rs0, 2);
        rs1 += __shfl_xor_sync(0xffffffffu, rs1, 1);
        rs1 += __shfl_xor_sync(0xffffffffu, rs1, 2);
        l0 = l0*a0 + rs0; l1 = l1*a1 + rs1;
        #pragma unroll
        for (int j = 0; j < 16; j++) {
            oacc[j][0] *= a0; oacc[j][1] *= a0;
            oacc[j][2] *= a1; oacc[j][3] *= a1;
        }

        // ---- O += P @ V  (x3)
        #pragma unroll
        for (int kk = 0; kk < 4; kk++) {
            uint32_t ph[4], pl[4];
            {
                const float* s0 = sacc[2*kk];
                const float* s1 = sacc[2*kk+1];
                __nv_bfloat16 hh, ll;
                __nv_bfloat16 h8[8], l8[8];
                spl(s0[0], h8[0], l8[0]); spl(s0[1], h8[1], l8[1]);
                spl(s0[2], h8[2], l8[2]); spl(s0[3], h8[3], l8[3]);
                spl(s1[0], h8[4], l8[4]); spl(s1[1], h8[5], l8[5]);
                spl(s1[2], h8[6], l8[6]); spl(s1[3], h8[7], l8[7]);
                (void)hh; (void)ll;
                ph[0] = pk2(h8[0], h8[1]); ph[1] = pk2(h8[2], h8[3]);
                ph[2] = pk2(h8[4], h8[5]); ph[3] = pk2(h8[6], h8[7]);
                pl[0] = pk2(l8[0], l8[1]); pl[1] = pk2(l8[2], l8[3]);
                pl[2] = pk2(l8[4], l8[5]); pl[3] = pk2(l8[6], l8[7]);
            }
            #pragma unroll
            for (int dg = 0; dg < 8; dg++) {
                uint32_t vh4[4], vl4[4];
                uint32_t ad = va + kk*(16*AT_STRIDE) + dg*32;
                ldsm_x4_t(vh4[0], vh4[1], vh4[2], vh4[3], ad);
                ldsm_x4_t(vl4[0], vl4[1], vl4[2], vl4[3], ad + AT_TILE);
                mma_bf16(oacc[2*dg],   pl, &vh4[0]);
                mma_bf16(oacc[2*dg],   ph, &vl4[0]);
                mma_bf16(oacc[2*dg],   ph, &vh4[0]);
                mma_bf16(oacc[2*dg+1], pl, &vh4[2]);
                mma_bf16(oacc[2*dg+1], ph, &vl4[2]);
                mma_bf16(oacc[2*dg+1], ph, &vh4[2]);
            }
        }
    }

    // ---- epilogue: normalize, stage fp32 tile, scrambled store
    __syncthreads();                                    // all warps done with K/V smem
    float* stg = (float*)(smem + 2*AT_TILE);            // overlay, stride 132 floats
    float i0 = 1.f / l0, i1 = 1.f / l1;
    #pragma unroll
    for (int j = 0; j < 16; j++) {
        int col = j*8 + t*2;
        *(float2*)&stg[(w*16 + g)*132 + col]     = make_float2(oacc[j][0]*i0, oacc[j][1]*i0);
        *(float2*)&stg[(w*16 + g + 8)*132 + col] = make_float2(oacc[j][2]*i1, oacc[j][3]*i1);
    }
    __syncthreads();

    const size_t obase = (size_t)b*SS*HH;
    for (int i = tid; i < 64*128; i += 128) {
        int d = i >> 6;
        int s = i & 63;
        size_t row = (size_t)h*64 + (d >> 1);
        size_t col = (size_t)(d & 1)*2048 + q0 + s;
        Outp[obase + row*HH + col] = stg[s*132 + d];
    }
}

// ---------------------------------------------------------------------------
extern "C" void kernel_launch(void* const* d_in, const int* in_sizes, int n_in,
                              void* d_out, int out_size)
{
    const float* X  = (const float*)d_in[0];
    const float* Wq = (const float*)d_in[1];
    const float* bq = (const float*)d_in[2];
    const float* Wk = (const float*)d_in[3];
    const float* bk = (const float*)d_in[4];
    const float* Wv = (const float*)d_in[5];
    const float* bv = (const float*)d_in[6];
    const float* Wo = (const float*)d_in[7];
    const float* bo = (const float*)d_in[8];
    float* out = (float*)d_out;

    float *Qp, *Kp, *Vp, *Ap, *Pp;
    __nv_bfloat16 *Xs, *Ws, *Ks, *Vs;
    cudaGetSymbolAddress((void**)&Qp, g_Q);
    cudaGetSymbolAddress((void**)&Kp, g_K);
    cudaGetSymbolAddress((void**)&Vp, g_V);
    cudaGetSymbolAddress((void**)&Ap, g_attn);
    cudaGetSymbolAddress((void**)&Pp, g_part);
    cudaGetSymbolAddress((void**)&Xs, g_Asplit);
    cudaGetSymbolAddress((void**)&Ws, g_Wsplit);
    cudaGetSymbolAddress((void**)&Ks, g_Ks);
    cudaGetSymbolAddress((void**)&Vs, g_Vs);

    __nv_bfloat16* Xh = Xs;
    __nv_bfloat16* Xl = Xs + (size_t)MTOT * HH;
    __nv_bfloat16* Wh = Ws;
    __nv_bfloat16* Wl = Ws + (size_t)HH * HH;
    __nv_bfloat16* Ksh = Ks;
    __nv_bfloat16* Ksl = Ks + (size_t)MTOT * DD;
    __nv_bfloat16* Vsh = Vs;
    __nv_bfloat16* Vsl = Vs + (size_t)MTOT * DD;

    cudaFuncSetAttribute(gemm_bf16x3,
                         cudaFuncAttributeMaxDynamicSharedMemorySize, GEMM_SMEM_BYTES);
    cudaFuncSetAttribute(mqa_attn_mma,
                         cudaFuncAttributeMaxDynamicSharedMemorySize, AT_SMEM);

    const int nX8 = MTOT*HH/8, nWqo8 = HH*HH/8, nWkv8 = DD*HH/8, nKV8 = MTOT*DD/8;
    const float qscale = 0.08838834764831845f;   // 1/sqrt(128)

    // 0) split X and Wq
    split_bf16<<<(nX8 + 255)/256, 256>>>(X, Xh, Xl, nX8, 1.f);
    split_bf16<<<(nWqo8 + 255)/256, 256>>>(Wq, Wh, Wl, nWqo8, 1.f);

    // 1) Q projection
    gemm_bf16x3<<<dim3(HH/128, MTOT/128, 1), 256, GEMM_SMEM_BYTES>>>(
        Xh, Xl, Wh, Wl, bq, Qp, MTOT, HH, HH, HH);

    // 2) K projection (split-K=4)
    split_bf16<<<(nWkv8 + 255)/256, 256>>>(Wk, Wh, Wl, nWkv8, 1.f);
    gemm_bf16x3<<<dim3(DD/128, MTOT/128, 4), 256, GEMM_SMEM_BYTES>>>(
        Xh, Xl, Wh, Wl, nullptr, Pp, MTOT, DD, HH, HH/4);
    reduce4_bias<<<(MTOT*DD + 255)/256, 256>>>(Pp, bk, Kp, MTOT*DD, DD);

    // 3) V projection (split-K=4)
    split_bf16<<<(nWkv8 + 255)/256, 256>>>(Wv, Wh, Wl, nWkv8, 1.f);
    gemm_bf16x3<<<dim3(DD/128, MTOT/128, 4), 256, GEMM_SMEM_BYTES>>>(
        Xh, Xl, Wh, Wl, nullptr, Pp, MTOT, DD, HH, HH/4);
    reduce4_bias<<<(MTOT*DD + 255)/256, 256>>>(Pp, bv, Vp, MTOT*DD, DD);

    // 4) split Q (scale folded; reuses g_Asplit — X split no longer needed),
    //    K and V into bf16 planes
    split_bf16<<<(nX8 + 255)/256, 256>>>(Qp, Xh, Xl, nX8, qscale);
    split_bf16<<<(nKV8 + 255)/256, 256>>>(Kp, Ksh, Ksl, nKV8, 1.f);
    split_bf16<<<(nKV8 + 255)/256, 256>>>(Vp, Vsh, Vsl, nKV8, 1.f);

    // 5) MMA flash attention -> scrambled fp32 layout
    mqa_attn_mma<<<dim3(SS/64, NHEAD, BB), 128, AT_SMEM>>>(
        Xh, Xl, Ksh, Ksl, Vsh, Vsl, Ap);

    // 6) O projection: split attn output and Wo, then GEMM
    split_bf16<<<(nX8 + 255)/256, 256>>>(Ap, Xh, Xl, nX8, 1.f);
    split_bf16<<<(nWqo8 + 255)/256, 256>>>(Wo, Wh, Wl, nWqo8, 1.f);
    gemm_bf16x3<<<dim3(HH/128, MTOT/128, 1), 256, GEMM_SMEM_BYTES>>>(
        Xh, Xl, Wh, Wl, bo, out, MTOT, HH, HH, HH);
}

// round 14
// speedup vs baseline: 3.5490x; 1.0095x over previous
#include <cuda_runtime.h>
#include <cuda_bf16.h>
#include <cstdint>
#include <math.h>

// Problem constants
#define BB    2
#define SS    2048
#define HH    4096
#define NHEAD 32
#define DD    128
#define MTOT  (BB*SS)

// Scratch (no cudaMalloc allowed)
__device__ float g_Q[(size_t)BB*SS*HH];        // 64 MB
__device__ float g_K[(size_t)BB*SS*DD];        // 2 MB
__device__ float g_V[(size_t)BB*SS*DD];        // 2 MB
__device__ float g_attn[(size_t)BB*SS*HH];     // 64 MB (scrambled layout)
__device__ float g_part[(size_t)4*MTOT*DD];    // 8 MB split-K partials
__device__ __nv_bfloat16 g_Asplit[(size_t)2*MTOT*HH];  // X/Q/attn splits (hi, lo planes)
__device__ __nv_bfloat16 g_Wsplit[(size_t)2*HH*HH];    // Wq split
__device__ __nv_bfloat16 g_Wsplit2[(size_t)2*HH*HH];   // Wo split
__device__ __nv_bfloat16 g_WsplitK[(size_t)2*DD*HH];   // Wk split
__device__ __nv_bfloat16 g_WsplitV[(size_t)2*DD*HH];   // Wv split
__device__ __nv_bfloat16 g_Ks[(size_t)2*MTOT*DD];      // K split planes
__device__ __nv_bfloat16 g_Vs[(size_t)2*MTOT*DD];      // V split planes

// ===========================================================================
// Helpers
// ===========================================================================
__device__ __forceinline__ uint32_t smem_u32(const void* p) {
    uint32_t a;
    asm("{ .reg .u64 t; cvta.to.shared.u64 t, %1; cvt.u32.u64 %0, t; }" : "=r"(a) : "l"(p));
    return a;
}
__device__ __forceinline__ void cp_async16(uint32_t dst, const void* src) {
    asm volatile("cp.async.cg.shared.global [%0], [%1], 16;" :: "r"(dst), "l"(src));
}
__device__ __forceinline__ void ldsm_x4(uint32_t& r0, uint32_t& r1, uint32_t& r2,
                                        uint32_t& r3, uint32_t addr) {
    asm volatile("ldmatrix.sync.aligned.m8n8.x4.shared.b16 {%0,%1,%2,%3}, [%4];"
                 : "=r"(r0), "=r"(r1), "=r"(r2), "=r"(r3) : "r"(addr));
}
__device__ __forceinline__ void ldsm_x4_t(uint32_t& r0, uint32_t& r1, uint32_t& r2,
                                          uint32_t& r3, uint32_t addr) {
    asm volatile("ldmatrix.sync.aligned.m8n8.x4.trans.shared.b16 {%0,%1,%2,%3}, [%4];"
                 : "=r"(r0), "=r"(r1), "=r"(r2), "=r"(r3) : "r"(addr));
}
// bf16 mma.sync: D(16x8) += A(16x16) @ B(8x16)^T, row.col, fp32 accum
__device__ __forceinline__ void mma_bf16(float* d, const uint32_t* a, const uint32_t* b) {
    asm volatile(
        "mma.sync.aligned.m16n8k16.row.col.f32.bf16.bf16.f32 "
        "{%0,%1,%2,%3}, {%4,%5,%6,%7}, {%8,%9}, {%0,%1,%2,%3};"
        : "+f"(d[0]), "+f"(d[1]), "+f"(d[2]), "+f"(d[3])
        : "r"(a[0]), "r"(a[1]), "r"(a[2]), "r"(a[3]), "r"(b[0]), "r"(b[1]));
}

__device__ __forceinline__ uint32_t pk2(__nv_bfloat16 a, __nv_bfloat16 b) {
    return (uint32_t)__bfloat16_as_ushort(a) | ((uint32_t)__bfloat16_as_ushort(b) << 16);
}
__device__ __forceinline__ void spl(float v, __nv_bfloat16& h, __nv_bfloat16& l) {
    h = __float2bfloat16(v);
    l = __float2bfloat16(v - __bfloat162float(h));
}

// ===========================================================================
// Pre-pass: split (scale * fp32) into two bf16 planes (hi, lo). 8 elems/thread.
// ===========================================================================
__global__ void __launch_bounds__(256)
split_bf16(const float* __restrict__ in, __nv_bfloat16* __restrict__ hi,
           __nv_bfloat16* __restrict__ lo, int n8, float scale)
{
    int i = blockIdx.x * 256 + threadIdx.x;
    if (i < n8) {
        const float4* p = (const float4*)in;
        float4 a = p[2*i], b = p[2*i+1];
        __nv_bfloat16 h[8], l[8];
        spl(a.x*scale, h[0], l[0]); spl(a.y*scale, h[1], l[1]);
        spl(a.z*scale, h[2], l[2]); spl(a.w*scale, h[3], l[3]);
        spl(b.x*scale, h[4], l[4]); spl(b.y*scale, h[5], l[5]);
        spl(b.z*scale, h[6], l[6]); spl(b.w*scale, h[7], l[7]);
        uint4 H, L;
        H.x = pk2(h[0], h[1]); H.y = pk2(h[2], h[3]);
        H.z = pk2(h[4], h[5]); H.w = pk2(h[6], h[7]);
        L.x = pk2(l[0], l[1]); L.y = pk2(l[2], l[3]);
        L.z = pk2(l[4], l[5]); L.w = pk2(l[6], l[7]);
        ((uint4*)hi)[i] = H;
        ((uint4*)lo)[i] = L;
    }
}

// ===========================================================================
// bf16x3 tensor-core GEMM (R12-validated core) + GROUP_M=16 supertile raster.
// Grid: (num_m*num_n, 1, splitZ). One wave (~296 CTAs) covers ~16x19 tiles
// -> A+B wave working set ~69MB < L2 -> B re-read 2x instead of 32x.
// ===========================================================================
#define ROWB 80
#define TILE_BYTES (128*ROWB)
#define STAGE_BYTES (4*TILE_BYTES)
#define GEMM_SMEM_BYTES (2*STAGE_BYTES)
#define GROUPM 16

__global__ void __launch_bounds__(256, 2)
gemm_bf16x3(const __nv_bfloat16* __restrict__ Ah, const __nv_bfloat16* __restrict__ Al,
            const __nv_bfloat16* __restrict__ Wh, const __nv_bfloat16* __restrict__ Wl,
            const float* __restrict__ bias, float* __restrict__ C,
            int M, int N, int Kdim, int kLen)
{
    extern __shared__ char smem[];
    const uint32_t smem_base = smem_u32(smem);

    const int tid = threadIdx.x;
    const int lane = tid & 31;
    const int wid = tid >> 5;
    const int g = lane >> 2;
    const int t = lane & 3;
    const int wm = wid & 1;
    const int wn = wid >> 1;

    // --- supertile rasterization ---
    const int num_n = N >> 7;
    const int num_m = M >> 7;
    const int pid = blockIdx.x;
    const int width = GROUPM * num_n;
    const int gid = pid / width;
    const int first_m = gid * GROUPM;
    const int gsz = min(num_m - first_m, GROUPM);
    const int pid_m = first_m + (pid % gsz);
    const int pid_n = (pid % width) / gsz;
    const int m0 = pid_m << 7;
    const int n0 = pid_n << 7;
    const int kOff = blockIdx.z * kLen;

    float acc[4][4][4];
    #pragma unroll
    for (int i = 0; i < 4; i++)
        #pragma unroll
        for (int j = 0; j < 4; j++)
            #pragma unroll
            for (int r = 0; r < 4; r++) acc[i][j][r] = 0.f;

    const int nch = kLen >> 5;
    const int crow = tid >> 2;
    const int ccol = tid & 3;

    const int a_row_l = (lane & 7) + ((lane >> 3) & 1) * 8;
    const int a_k16   = (lane >> 4) * 16;
    const int b_row_l = (lane >> 4) * 8 + (lane & 7);
    const int b_k16   = ((lane >> 3) & 1) * 16;

    auto stage = [&](int cidx, uint32_t dstbase) {
        const size_t kb = (size_t)kOff + (size_t)cidx * 32 + ccol * 8;
        #pragma unroll
        for (int p = 0; p < 2; p++) {
            int r = crow + 64 * p;
            uint32_t d = dstbase + (uint32_t)(r * ROWB + ccol * 16);
            cp_async16(d,                 Ah + (size_t)(m0 + r) * Kdim + kb);
            cp_async16(d +   TILE_BYTES,  Al + (size_t)(m0 + r) * Kdim + kb);
            cp_async16(d + 2*TILE_BYTES,  Wh + (size_t)(n0 + r) * Kdim + kb);
            cp_async16(d + 3*TILE_BYTES,  Wl + (size_t)(n0 + r) * Kdim + kb);
        }
    };

    stage(0, smem_base);
    asm volatile("cp.async.commit_group;" ::: "memory");

    for (int c = 0; c < nch; c++) {
        if (c + 1 < nch) {
            stage(c + 1, smem_base + (uint32_t)((c + 1) & 1) * STAGE_BYTES);
            asm volatile("cp.async.commit_group;" ::: "memory");
            asm volatile("cp.async.wait_group 1;" ::: "memory");
        } else {
            asm volatile("cp.async.wait_group 0;" ::: "memory");
        }
        __syncthreads();

        const uint32_t sb = smem_base + (uint32_t)(c & 1) * STAGE_BYTES;
        const uint32_t aBase = sb + (uint32_t)((wm * 64 + a_row_l) * ROWB + a_k16);
        const uint32_t bBase = sb + 2*TILE_BYTES
                             + (uint32_t)((wn * 32 + b_row_l) * ROWB + b_k16);

        #pragma unroll
        for (int ks = 0; ks < 2; ks++) {
            uint32_t bh[4][2], bl[4][2];
            #pragma unroll
            for (int tnp = 0; tnp < 2; tnp++) {
                uint32_t ad = bBase + tnp * (16 * ROWB) + ks * 32;
                ldsm_x4(bh[2*tnp][0], bh[2*tnp][1], bh[2*tnp+1][0], bh[2*tnp+1][1], ad);
                ldsm_x4(bl[2*tnp][0], bl[2*tnp][1], bl[2*tnp+1][0], bl[2*tnp+1][1],
                        ad + TILE_BYTES);
            }
            #pragma unroll
            for (int mh = 0; mh < 2; mh++) {
                uint32_t ah[2][4], al[2][4];
                #pragma unroll
                for (int q = 0; q < 2; q++) {
                    uint32_t ad = aBase + (mh * 2 + q) * (16 * ROWB) + ks * 32;
                    ldsm_x4(ah[q][0], ah[q][1], ah[q][2], ah[q][3], ad);
                    ldsm_x4(al[q][0], al[q][1], al[q][2], al[q][3], ad + TILE_BYTES);
                }
                #pragma unroll
                for (int q = 0; q < 2; q++)
                    #pragma unroll
                    for (int tn = 0; tn < 4; tn++) {
                        float* d = acc[mh * 2 + q][tn];
                        mma_bf16(d, al[q], bh[tn]);
                        mma_bf16(d, ah[q], bl[tn]);
                        mma_bf16(d, ah[q], bh[tn]);
                    }
            }
        }
        __syncthreads();
    }

    const bool full = (gridDim.z == 1);
    float* Cout = C + (full ? (size_t)0 : (size_t)blockIdx.z * M * N);
    #pragma unroll
    for (int mt = 0; mt < 4; mt++) {
        int row = m0 + wm * 64 + mt * 16 + g;
        #pragma unroll
        for (int tn = 0; tn < 4; tn++) {
            int col = n0 + wn * 32 + tn * 8 + t * 2;
            float bx = 0.f, by = 0.f;
            if (full) { float2 bv = *(const float2*)(bias + col); bx = bv.x; by = bv.y; }
            float2 v0, v1;
            v0.x = acc[mt][tn][0] + bx; v0.y = acc[mt][tn][1] + by;
            v1.x = acc[mt][tn][2] + bx; v1.y = acc[mt][tn][3] + by;
            *(float2*)(Cout + (size_t)row * N + col) = v0;
            *(float2*)(Cout + (size_t)(row + 8) * N + col) = v1;
        }
    }
}

// Deterministic split-K reduce
__global__ void __launch_bounds__(256)
reduce4_bias(const float* __restrict__ part, const float* __restrict__ bias,
             float* __restrict__ out, int MN, int N)
{
    int i = blockIdx.x * 256 + threadIdx.x;
    if (i < MN) {
        float v = (part[i] + part[(size_t)MN + i])
                + (part[(size_t)2*MN + i] + part[(size_t)3*MN + i]);
        out[i] = v + bias[i & (N - 1)];
    }
}

// ===========================================================================
// bf16x3 MMA flash attention (R13-validated, unchanged)
// ===========================================================================
#define AT_STRIDE 272
#define AT_TILE  (64*AT_STRIDE)
#define AT_SMEM  (6*AT_TILE)

__global__ void __launch_bounds__(128, 2)
mqa_attn_mma(const __nv_bfloat16* __restrict__ Qh, const __nv_bfloat16* __restrict__ Ql,
             const __nv_bfloat16* __restrict__ Kh, const __nv_bfloat16* __restrict__ Kl,
             const __nv_bfloat16* __restrict__ Vh, const __nv_bfloat16* __restrict__ Vl,
             float* __restrict__ Outp)
{
    extern __shared__ char smem[];
    const uint32_t sb = smem_u32(smem);
    const int tid = threadIdx.x;
    const int w = tid >> 5;
    const int lane = tid & 31;
    const int g = lane >> 2, t = lane & 3;
    const int q0 = blockIdx.x * 64;
    const int h = blockIdx.y;
    const int b = blockIdx.z;

    const uint32_t SQh = sb, SQl = sb + AT_TILE, SKh = sb + 2*AT_TILE,
                   SKl = sb + 3*AT_TILE, SVh = sb + 4*AT_TILE, SVl = sb + 5*AT_TILE;

    {
        const size_t qg = ((size_t)(b*SS + q0))*HH + (size_t)h*DD;
        for (int i = tid; i < 64*16; i += 128) {
            int r = i >> 4, ch = i & 15;
            size_t src = qg + (size_t)r*HH + ch*8;
            uint32_t dst = (uint32_t)(r*AT_STRIDE + ch*16);
            cp_async16(SQh + dst, Qh + src);
            cp_async16(SQl + dst, Ql + src);
        }
        asm volatile("cp.async.commit_group;" ::: "memory");
    }

    float m0 = -INFINITY, m1 = -INFINITY, l0 = 0.f, l1 = 0.f;
    float oacc[16][4];
    #pragma unroll
    for (int j = 0; j < 16; j++)
        #pragma unroll
        for (int r = 0; r < 4; r++) oacc[j][r] = 0.f;

    const uint32_t qa = SQh + (uint32_t)((w*16 + (lane&7) + ((lane>>3)&1)*8)*AT_STRIDE
                                         + ((lane>>4)&1)*16);
    const uint32_t kb = SKh + (uint32_t)(((lane>>4)*8 + (lane&7))*AT_STRIDE
                                         + ((lane>>3)&1)*16);
    const uint32_t va = SVh + (uint32_t)(((lane&7) + ((lane>>3)&1)*8)*AT_STRIDE
                                         + ((lane>>4)&1)*16);

    const size_t kvg0 = (size_t)(b*SS)*DD;

    for (int kt = 0; kt < SS/64; kt++) {
        __syncthreads();
        for (int i = tid; i < 64*16; i += 128) {
            int r = i >> 4, ch = i & 15;
            size_t src = kvg0 + (size_t)(kt*64 + r)*DD + ch*8;
            uint32_t dst = (uint32_t)(r*AT_STRIDE + ch*16);
            cp_async16(SKh + dst, Kh + src);
            cp_async16(SKl + dst, Kl + src);
            cp_async16(SVh + dst, Vh + src);
            cp_async16(SVl + dst, Vl + src);
        }
        asm volatile("cp.async.commit_group;" ::: "memory");
        asm volatile("cp.async.wait_group 0;" ::: "memory");
        __syncthreads();

        float sacc[8][4];
        #pragma unroll
        for (int j = 0; j < 8; j++)
            #pragma unroll
            for (int r = 0; r < 4; r++) sacc[j][r] = 0.f;

        #pragma unroll
        for (int ks = 0; ks < 8; ks++) {
            uint32_t qh_[4], ql_[4];
            ldsm_x4(qh_[0], qh_[1], qh_[2], qh_[3], qa + ks*32);
            ldsm_x4(ql_[0], ql_[1], ql_[2], ql_[3], qa + AT_TILE + ks*32);
            #pragma unroll
            for (int np = 0; np < 4; np++) {
                uint32_t kh4[4], kl4[4];
                uint32_t ad = kb + np*(16*AT_STRIDE) + ks*32;
                ldsm_x4(kh4[0], kh4[1], kh4[2], kh4[3], ad);
                ldsm_x4(kl4[0], kl4[1], kl4[2], kl4[3], ad + AT_TILE);
                mma_bf16(sacc[2*np],   ql_, &kh4[0]);
                mma_bf16(sacc[2*np],   qh_, &kl4[0]);
                mma_bf16(sacc[2*np],   qh_, &kh4[0]);
                mma_bf16(sacc[2*np+1], ql_, &kh4[2]);
                mma_bf16(sacc[2*np+1], qh_, &kl4[2]);
                mma_bf16(sacc[2*np+1], qh_, &kh4[2]);
            }
        }

        float rx0 = -INFINITY, rx1 = -INFINITY;
        #pragma unroll
        for (int j = 0; j < 8; j++) {
            rx0 = fmaxf(rx0, fmaxf(sacc[j][0], sacc[j][1]));
            rx1 = fmaxf(rx1, fmaxf(sacc[j][2], sacc[j][3]));
        }
        rx0 = fmaxf(rx0, __shfl_xor_sync(0xffffffffu, rx0, 1));
        rx0 = fmaxf(rx0, __shfl_xor_sync(0xffffffffu, rx0, 2));
        rx1 = fmaxf(rx1, __shfl_xor_sync(0xffffffffu, rx1, 1));
        rx1 = fmaxf(rx1, __shfl_xor_sync(0xffffffffu, rx1, 2));
        float mn0 = fmaxf(m0, rx0), mn1 = fmaxf(m1, rx1);
        float a0 = __expf(m0 - mn0), a1 = __expf(m1 - mn1);
        m0 = mn0; m1 = mn1;
        float rs0 = 0.f, rs1 = 0.f;
        #pragma unroll
        for (int j = 0; j < 8; j++) {
            sacc[j][0] = __expf(sacc[j][0] - mn0);
            sacc[j][1] = __expf(sacc[j][1] - mn0);
            sacc[j][2] = __expf(sacc[j][2] - mn1);
            sacc[j][3] = __expf(sacc[j][3] - mn1);
            rs0 += sacc[j][0] + sacc[j][1];
            rs1 += sacc[j][2] + sacc[j][3];
        }
        rs0 += __shfl_xor_sync(0xffffffffu, rs0, 1);
        rs0 += __shfl_xor_sync(0xffffffffu, rs0, 2);
        rs1 += __shfl_xor_sync(0xffffffffu, rs1, 1);
        rs1 += __shfl_xor_sync(0xffffffffu, rs1, 2);
        l0 = l0*a0 + rs0; l1 = l1*a1 + rs1;
        #pragma unroll
        for (int j = 0; j < 16; j++) {
            oacc[j][0] *= a0; oacc[j][1] *= a0;
            oacc[j][2] *= a1; oacc[j][3] *= a1;
        }

        #pragma unroll
        for (int kk = 0; kk < 4; kk++) {
            uint32_t ph[4], pl[4];
            {
                const float* s0 = sacc[2*kk];
                const float* s1 = sacc[2*kk+1];
                __nv_bfloat16 h8[8], l8[8];
                spl(s0[0], h8[0], l8[0]); spl(s0[1], h8[1], l8[1]);
                spl(s0[2], h8[2], l8[2]); spl(s0[3], h8[3], l8[3]);
                spl(s1[0], h8[4], l8[4]); spl(s1[1], h8[5], l8[5]);
                spl(s1[2], h8[6], l8[6]); spl(s1[3], h8[7], l8[7]);
                ph[0] = pk2(h8[0], h8[1]); ph[1] = pk2(h8[2], h8[3]);
                ph[2] = pk2(h8[4], h8[5]); ph[3] = pk2(h8[6], h8[7]);
                pl[0] = pk2(l8[0], l8[1]); pl[1] = pk2(l8[2], l8[3]);
                pl[2] = pk2(l8[4], l8[5]); pl[3] = pk2(l8[6], l8[7]);
            }
            #pragma unroll
            for (int dg = 0; dg < 8; dg++) {
                uint32_t vh4[4], vl4[4];
                uint32_t ad = va + kk*(16*AT_STRIDE) + dg*32;
                ldsm_x4_t(vh4[0], vh4[1], vh4[2], vh4[3], ad);
                ldsm_x4_t(vl4[0], vl4[1], vl4[2], vl4[3], ad + AT_TILE);
                mma_bf16(oacc[2*dg],   pl, &vh4[0]);
                mma_bf16(oacc[2*dg],   ph, &vl4[0]);
                mma_bf16(oacc[2*dg],   ph, &vh4[0]);
                mma_bf16(oacc[2*dg+1], pl, &vh4[2]);
                mma_bf16(oacc[2*dg+1], ph, &vl4[2]);
                mma_bf16(oacc[2*dg+1], ph, &vh4[2]);
            }
        }
    }

    __syncthreads();
    float* stg = (float*)(smem + 2*AT_TILE);
    float i0 = 1.f / l0, i1 = 1.f / l1;
    #pragma unroll
    for (int j = 0; j < 16; j++) {
        int col = j*8 + t*2;
        *(float2*)&stg[(w*16 + g)*132 + col]     = make_float2(oacc[j][0]*i0, oacc[j][1]*i0);
        *(float2*)&stg[(w*16 + g + 8)*132 + col] = make_float2(oacc[j][2]*i1, oacc[j][3]*i1);
    }
    __syncthreads();

    const size_t obase = (size_t)b*SS*HH;
    for (int i = tid; i < 64*128; i += 128) {
        int d = i >> 6;
        int s = i & 63;
        size_t row = (size_t)h*64 + (d >> 1);
        size_t col = (size_t)(d & 1)*2048 + q0 + s;
        Outp[obase + row*HH + col] = stg[s*132 + d];
    }
}

// ---------------------------------------------------------------------------
extern "C" void kernel_launch(void* const* d_in, const int* in_sizes, int n_in,
                              void* d_out, int out_size)
{
    const float* X  = (const float*)d_in[0];
    const float* Wq = (const float*)d_in[1];
    const float* bq = (const float*)d_in[2];
    const float* Wk = (const float*)d_in[3];
    const float* bk = (const float*)d_in[4];
    const float* Wv = (const float*)d_in[5];
    const float* bv = (const float*)d_in[6];
    const float* Wo = (const float*)d_in[7];
    const float* bo = (const float*)d_in[8];
    float* out = (float*)d_out;

    float *Qp, *Kp, *Vp, *Ap, *Pp;
    __nv_bfloat16 *Xs, *Wq_s, *Wo_s, *Wk_s, *Wv_s, *Ks, *Vs;
    cudaGetSymbolAddress((void**)&Qp, g_Q);
    cudaGetSymbolAddress((void**)&Kp, g_K);
    cudaGetSymbolAddress((void**)&Vp, g_V);
    cudaGetSymbolAddress((void**)&Ap, g_attn);
    cudaGetSymbolAddress((void**)&Pp, g_part);
    cudaGetSymbolAddress((void**)&Xs, g_Asplit);
    cudaGetSymbolAddress((void**)&Wq_s, g_Wsplit);
    cudaGetSymbolAddress((void**)&Wo_s, g_Wsplit2);
    cudaGetSymbolAddress((void**)&Wk_s, g_WsplitK);
    cudaGetSymbolAddress((void**)&Wv_s, g_WsplitV);
    cudaGetSymbolAddress((void**)&Ks, g_Ks);
    cudaGetSymbolAddress((void**)&Vs, g_Vs);

    __nv_bfloat16* Xh = Xs;
    __nv_bfloat16* Xl = Xs + (size_t)MTOT * HH;
    __nv_bfloat16* Wqh = Wq_s;  __nv_bfloat16* Wql = Wq_s + (size_t)HH * HH;
    __nv_bfloat16* Woh = Wo_s;  __nv_bfloat16* Wol = Wo_s + (size_t)HH * HH;
    __nv_bfloat16* Wkh = Wk_s;  __nv_bfloat16* Wkl = Wk_s + (size_t)DD * HH;
    __nv_bfloat16* Wvh = Wv_s;  __nv_bfloat16* Wvl = Wv_s + (size_t)DD * HH;
    __nv_bfloat16* Ksh = Ks;    __nv_bfloat16* Ksl = Ks + (size_t)MTOT * DD;
    __nv_bfloat16* Vsh = Vs;    __nv_bfloat16* Vsl = Vs + (size_t)MTOT * DD;

    cudaFuncSetAttribute(gemm_bf16x3,
                         cudaFuncAttributeMaxDynamicSharedMemorySize, GEMM_SMEM_BYTES);
    cudaFuncSetAttribute(mqa_attn_mma,
                         cudaFuncAttributeMaxDynamicSharedMemorySize, AT_SMEM);

    const int nX8 = MTOT*HH/8, nWqo8 = HH*HH/8, nWkv8 = DD*HH/8, nKV8 = MTOT*DD/8;
    const float qscale = 0.08838834764831845f;   // 1/sqrt(128)

    // 0) all input splits up front (launches 1-5; makes the big GEMM launch #6
    //    so ncu's -s 5 -c 1 captures it)
    split_bf16<<<(nX8 + 255)/256, 256>>>(X, Xh, Xl, nX8, 1.f);
    split_bf16<<<(nWqo8 + 255)/256, 256>>>(Wq, Wqh, Wql, nWqo8, 1.f);
    split_bf16<<<(nWkv8 + 255)/256, 256>>>(Wk, Wkh, Wkl, nWkv8, 1.f);
    split_bf16<<<(nWkv8 + 255)/256, 256>>>(Wv, Wvh, Wvl, nWkv8, 1.f);
    split_bf16<<<(nWqo8 + 255)/256, 256>>>(Wo, Woh, Wol, nWqo8, 1.f);

    // 1) Q projection (supertile raster, flat grid)
    gemm_bf16x3<<<dim3((HH/128)*(MTOT/128), 1, 1), 256, GEMM_SMEM_BYTES>>>(
        Xh, Xl, Wqh, Wql, bq, Qp, MTOT, HH, HH, HH);

    // 2) K projection (split-K=4)
    gemm_bf16x3<<<dim3((DD/128)*(MTOT/128), 1, 4), 256, GEMM_SMEM_BYTES>>>(
        Xh, Xl, Wkh, Wkl, nullptr, Pp, MTOT, DD, HH, HH/4);
    reduce4_bias<<<(MTOT*DD + 255)/256, 256>>>(Pp, bk, Kp, MTOT*DD, DD);

    // 3) V projection (split-K=4)
    gemm_bf16x3<<<dim3((DD/128)*(MTOT/128), 1, 4), 256, GEMM_SMEM_BYTES>>>(
        Xh, Xl, Wvh, Wvl, nullptr, Pp, MTOT, DD, HH, HH/4);
    reduce4_bias<<<(MTOT*DD + 255)/256, 256>>>(Pp, bv, Vp, MTOT*DD, DD);

    // 4) split Q (scale folded; reuses g_Asplit), K, V
    split_bf16<<<(nX8 + 255)/256, 256>>>(Qp, Xh, Xl, nX8, qscale);
    split_bf16<<<(nKV8 + 255)/256, 256>>>(Kp, Ksh, Ksl, nKV8, 1.f);
    split_bf16<<<(nKV8 + 255)/256, 256>>>(Vp, Vsh, Vsl, nKV8, 1.f);

    // 5) MMA flash attention -> scrambled fp32 layout
    mqa_attn_mma<<<dim3(SS/64, NHEAD, BB), 128, AT_SMEM>>>(
        Xh, Xl, Ksh, Ksl, Vsh, Vsl, Ap);

    // 6) O projection: split attn output, then GEMM
    split_bf16<<<(nX8 + 255)/256, 256>>>(Ap, Xh, Xl, nX8, 1.f);
    gemm_bf16x3<<<dim3((HH/128)*(MTOT/128), 1, 1), 256, GEMM_SMEM_BYTES>>>(
        Xh, Xl, Woh, Wol, bo, out, MTOT, HH, HH, HH);
}